// round 5
// baseline (speedup 1.0000x reference)
#include <cuda_runtime.h>
#include <math.h>
#include <stdint.h>

#define BATCH   2
#define SEQ     2048
#define DMODEL  1024
#define NHEADS  16
#define HDIM    64
#define M_ROWS  (BATCH*SEQ)
#define ROPE_SCALE 0.006135923151542565f      // 2*pi/1024
#define LOG2_1E4_OVER16 0.830482023721841f    // log2(10000)/16

// Scratch (device globals: allocation-free)
__device__ float g_q[BATCH*NHEADS*SEQ*HDIM];   // [B,H,N,D]
__device__ float g_k[BATCH*NHEADS*SEQ*HDIM];
__device__ float g_v[BATCH*NHEADS*SEQ*HDIM];
__device__ float g_o[BATCH*SEQ*DMODEL];        // [B,N,d]

// ---------------------------------------------------------------------------
// helpers
// ---------------------------------------------------------------------------
__device__ __forceinline__ uint32_t f2tf(float x) {
    uint32_t u;
    asm("cvt.rna.tf32.f32 %0, %1;" : "=r"(u) : "f"(x));
    return u;
}

__device__ __forceinline__ float fast_exp2(float x) {
    float y;
    asm("ex2.approx.f32 %0, %1;" : "=f"(y) : "f"(x));
    return y;
}

__device__ __forceinline__ void mma_tf32(float c[4],
        uint32_t a0, uint32_t a1, uint32_t a2, uint32_t a3,
        uint32_t b0, uint32_t b1)
{
    asm volatile(
        "mma.sync.aligned.m16n8k8.row.col.f32.tf32.tf32.f32 "
        "{%0,%1,%2,%3}, {%4,%5,%6,%7}, {%8,%9}, {%0,%1,%2,%3};\n"
        : "+f"(c[0]), "+f"(c[1]), "+f"(c[2]), "+f"(c[3])
        : "r"(a0), "r"(a1), "r"(a2), "r"(a3), "r"(b0), "r"(b1));
}

// ---------------------------------------------------------------------------
// GEMM with fragment-ordered smem. C = A[M][K] * W[N][K]^T + bias (+rope)
// BM=BN=128, BK=32, 256 threads (8 warps, 2x4), warp tile 64x32.
// Fragment layout:
//   A tiles (rb over 128 rows /16, kbi=0..3): 32 lanes x 4 words -> LDS.128.
//   B tiles (nb over 128 cols /8, kbi): 32 lanes x 2 words -> LDS.64.
// ---------------------------------------------------------------------------
struct GemmArgs {
    const float* A;
    const float* W[3];
    const float* bias[3];
    float*       C[3];
    const float* pos[3];   // non-null => apply rope in epilogue (layout_bhnd only)
    int layout_bhnd;       // 1 -> scatter [B,H,N,D]; 0 -> row-major [M][1024]
};

#define AFT 136   // A fragment-tile stride in words (128 + 8 pad; 16B-aligned)
#define BFT 72    // B fragment-tile stride in words (64 + 8 pad; 8B-aligned)

__global__ __launch_bounds__(256)
void gemm_tf32_kernel(GemmArgs args)
{
    __shared__ __align__(16) uint32_t Af[32 * AFT];   // 8 rb * 4 kbi tiles
    __shared__ __align__(16) uint32_t Bf[64 * BFT];   // 16 nb * 4 kbi tiles

    const int tid  = threadIdx.x;
    const int warp = tid >> 5;
    const int lane = tid & 31;
    const int wm = (warp & 1) * 64;
    const int wn = (warp >> 1) * 32;
    const int proj = blockIdx.x >> 3;
    const int bn = (blockIdx.x & 7) * 128;
    const int bm = blockIdx.y * 128;

    const float* A    = args.A;
    const float* W    = args.W[proj];
    const float* bias = args.bias[proj];
    float*       C    = args.C[proj];
    const float* pos  = args.pos[proj];

    // loader mapping: rows lr+32i, float4 at col lc
    const int lr = tid >> 3;           // 0..31
    const int lc = (tid & 7) * 4;      // 0..28
    const int kb = lc >> 3;            // k-block within BK
    const int kh = (lc >> 2) & 1;      // k half within block

    const float* Aptr = A + (size_t)(bm + lr) * DMODEL + lc;
    const float* Wptr = W + (size_t)(bn + lr) * DMODEL + lc;

    // per-pass fragment store bases (constant across k0)
    int abase[4], bbase[4];
#pragma unroll
    for (int i = 0; i < 4; i++) {
        int m = lr + 32 * i;
        abase[i] = ((m >> 4) * 4 + kb) * AFT + (m & 7) * 16 + ((m >> 3) & 1) + 2 * kh;
        bbase[i] = ((m >> 3) * 4 + kb) * BFT + (m & 7) * 8 + kh;
    }

    float4 pa[4], pb[4];
#pragma unroll
    for (int i = 0; i < 4; i++) {
        pa[i] = *(const float4*)(Aptr + (size_t)i * 32 * DMODEL);
        pb[i] = *(const float4*)(Wptr + (size_t)i * 32 * DMODEL);
    }

    float acc[4][4][4];
#pragma unroll
    for (int mt = 0; mt < 4; mt++)
#pragma unroll
        for (int nt = 0; nt < 4; nt++)
#pragma unroll
            for (int r = 0; r < 4; r++) acc[mt][nt][r] = 0.f;

    for (int k0 = 0; k0 < DMODEL; k0 += 32) {
#pragma unroll
        for (int i = 0; i < 4; i++) {
            uint32_t* a = Af + abase[i];
            a[0]  = f2tf(pa[i].x); a[4]  = f2tf(pa[i].y);
            a[8]  = f2tf(pa[i].z); a[12] = f2tf(pa[i].w);
            uint32_t* b = Bf + bbase[i];
            b[0] = f2tf(pb[i].x); b[2] = f2tf(pb[i].y);
            b[4] = f2tf(pb[i].z); b[6] = f2tf(pb[i].w);
        }
        __syncthreads();

        if (k0 + 32 < DMODEL) {
#pragma unroll
            for (int i = 0; i < 4; i++) {
                pa[i] = *(const float4*)(Aptr + (size_t)i * 32 * DMODEL + k0 + 32);
                pb[i] = *(const float4*)(Wptr + (size_t)i * 32 * DMODEL + k0 + 32);
            }
        }

#pragma unroll
        for (int kbi = 0; kbi < 4; kbi++) {
            uint4 afr[4];
            uint2 bfr[4];
#pragma unroll
            for (int mt = 0; mt < 4; mt++)
                afr[mt] = *(const uint4*)&Af[(((wm >> 4) + mt) * 4 + kbi) * AFT + lane * 4];
#pragma unroll
            for (int nt = 0; nt < 4; nt++)
                bfr[nt] = *(const uint2*)&Bf[(((wn >> 3) + nt) * 4 + kbi) * BFT + lane * 2];
#pragma unroll
            for (int nt = 0; nt < 4; nt++)
#pragma unroll
                for (int mt = 0; mt < 4; mt++)
                    mma_tf32(acc[mt][nt], afr[mt].x, afr[mt].y, afr[mt].z, afr[mt].w,
                             bfr[nt].x, bfr[nt].y);
        }
        __syncthreads();
    }

    // epilogue: bias (+rope) (+layout scatter)
#pragma unroll
    for (int nt = 0; nt < 4; nt++) {
        int cg = bn + wn + nt * 8 + 2 * (lane & 3);
        float bv0 = bias[cg], bv1 = bias[cg + 1];
        int dd = cg & 63;
        int hh = (cg >> 6) & (NHEADS - 1);
        int ip = (dd & 31) >> 1;
        int plane = (dd >> 5) & 1;
        float invf = fast_exp2(-LOG2_1E4_OVER16 * (float)ip) * ROPE_SCALE;
#pragma unroll
        for (int mt = 0; mt < 4; mt++) {
            int r0 = bm + wm + mt * 16 + (lane >> 2);
#pragma unroll
            for (int rr = 0; rr < 2; rr++) {
                int r = r0 + rr * 8;
                float v0 = acc[mt][nt][rr * 2 + 0] + bv0;
                float v1 = acc[mt][nt][rr * 2 + 1] + bv1;
                if (args.layout_bhnd) {
                    int b = r >> 11, n = r & 2047;
                    if (pos) {
                        float ang = pos[((size_t)(b * SEQ + n)) * 2 + plane] * invf;
                        float sn, cs;
                        __sincosf(ang, &sn, &cs);
                        float y0 = v0 * cs - v1 * sn;
                        float y1 = v0 * sn + v1 * cs;
                        v0 = y0; v1 = y1;
                    }
                    size_t base = (((size_t)(b * NHEADS + hh)) * SEQ + n) * HDIM + dd;
                    C[base] = v0; C[base + 1] = v1;
                } else {
                    *(float2*)&C[(size_t)r * DMODEL + cg] = make_float2(v0, v1);
                }
            }
        }
    }
}

// ---------------------------------------------------------------------------
// Flash attention, tf32 mma, mt=2: 4 warps x (32x64 warp tile) = 128 q-rows/CTA.
// K tiles 64 keys, double softmax state per warp row-block.
// ---------------------------------------------------------------------------
#define KS_STRIDE 68
#define VS_STRIDE 72
#define PS_STRIDE 68
#define ATTN_SMEM ((64*KS_STRIDE + 64*VS_STRIDE + 4*32*PS_STRIDE) * 4)

__global__ __launch_bounds__(128)
void attn_tf32_kernel(const float* __restrict__ Q, const float* __restrict__ Kg,
                      const float* __restrict__ Vg, float* __restrict__ O)
{
    extern __shared__ uint32_t sm[];
    uint32_t* Ks = sm;                                   // [key][dim] stride 68
    uint32_t* Vs = sm + 64 * KS_STRIDE;                  // [key][dim] stride 72
    uint32_t* Ps = sm + 64 * KS_STRIDE + 64 * VS_STRIDE; // per-warp 32x68

    const int tid  = threadIdx.x;
    const int warp = tid >> 5;
    const int lane = tid & 31;
    const int qb = blockIdx.x & 15;    // 16 q-blocks of 128 per (b,h)
    const int bh = blockIdx.x >> 4;

    uint32_t* Pw = Ps + warp * 32 * PS_STRIDE;

    // Q fragments (scaled by 1/8, rna-tf32), rows warp*32 + mt*16 ...
    const float* qbase = Q + ((size_t)bh * SEQ + qb * 128) * HDIM;
    uint32_t qf[2][8][4];
#pragma unroll
    for (int mt = 0; mt < 2; mt++) {
        int r = warp * 32 + mt * 16 + (lane >> 2);
#pragma unroll
        for (int ks = 0; ks < 8; ks++) {
            int c = ks * 8 + (lane & 3);
            qf[mt][ks][0] = f2tf(qbase[(size_t)r * HDIM + c] * 0.125f);
            qf[mt][ks][1] = f2tf(qbase[(size_t)(r + 8) * HDIM + c] * 0.125f);
            qf[mt][ks][2] = f2tf(qbase[(size_t)r * HDIM + c + 4] * 0.125f);
            qf[mt][ks][3] = f2tf(qbase[(size_t)(r + 8) * HDIM + c + 4] * 0.125f);
        }
    }

    float m[2][2], l[2][2];
    float o[2][8][4];
#pragma unroll
    for (int mt = 0; mt < 2; mt++) {
        m[mt][0] = -1e30f; m[mt][1] = -1e30f;
        l[mt][0] = 0.f;    l[mt][1] = 0.f;
#pragma unroll
        for (int nt = 0; nt < 8; nt++)
#pragma unroll
            for (int r = 0; r < 4; r++) o[mt][nt][r] = 0.f;
    }

    const float* kbp = Kg + (size_t)bh * SEQ * HDIM;
    const float* vbp = Vg + (size_t)bh * SEQ * HDIM;

    const int lr  = tid >> 4;          // 0..7
    const int lc4 = (tid & 15) * 4;    // 0..60

    for (int kt = 0; kt < SEQ; kt += 64) {
        __syncthreads();
#pragma unroll
        for (int i = 0; i < 8; i++) {
            int r = lr + i * 8;
            float4 kv = *(const float4*)(kbp + (size_t)(kt + r) * HDIM + lc4);
            float4 vv = *(const float4*)(vbp + (size_t)(kt + r) * HDIM + lc4);
            uint32_t* kd = Ks + r * KS_STRIDE + lc4;
            kd[0] = f2tf(kv.x); kd[1] = f2tf(kv.y); kd[2] = f2tf(kv.z); kd[3] = f2tf(kv.w);
            uint32_t* vd = Vs + r * VS_STRIDE + lc4;
            vd[0] = f2tf(vv.x); vd[1] = f2tf(vv.y); vd[2] = f2tf(vv.z); vd[3] = f2tf(vv.w);
        }
        __syncthreads();

        // GEMM1: S = Q * K^T (each warp 32x64; B-frags shared across mt)
        float s[2][8][4];
#pragma unroll
        for (int mt = 0; mt < 2; mt++)
#pragma unroll
            for (int nt = 0; nt < 8; nt++)
#pragma unroll
                for (int r = 0; r < 4; r++) s[mt][nt][r] = 0.f;

#pragma unroll
        for (int ks = 0; ks < 8; ks++) {
            int q = ks * 8 + (lane & 3);
#pragma unroll
            for (int nt = 0; nt < 8; nt++) {
                int n0 = nt * 8 + (lane >> 2);
                uint32_t b0 = Ks[n0 * KS_STRIDE + q];
                uint32_t b1 = Ks[n0 * KS_STRIDE + q + 4];
                mma_tf32(s[0][nt], qf[0][ks][0], qf[0][ks][1], qf[0][ks][2], qf[0][ks][3], b0, b1);
                mma_tf32(s[1][nt], qf[1][ks][0], qf[1][ks][1], qf[1][ks][2], qf[1][ks][3], b0, b1);
            }
        }

        // online softmax + P store, per mt
#pragma unroll
        for (int mt = 0; mt < 2; mt++) {
            float rm0 = -1e30f, rm1 = -1e30f;
#pragma unroll
            for (int nt = 0; nt < 8; nt++) {
                rm0 = fmaxf(rm0, fmaxf(s[mt][nt][0], s[mt][nt][1]));
                rm1 = fmaxf(rm1, fmaxf(s[mt][nt][2], s[mt][nt][3]));
            }
            rm0 = fmaxf(rm0, __shfl_xor_sync(0xffffffffu, rm0, 1));
            rm0 = fmaxf(rm0, __shfl_xor_sync(0xffffffffu, rm0, 2));
            rm1 = fmaxf(rm1, __shfl_xor_sync(0xffffffffu, rm1, 1));
            rm1 = fmaxf(rm1, __shfl_xor_sync(0xffffffffu, rm1, 2));

            float mn0 = fmaxf(m[mt][0], rm0), mn1 = fmaxf(m[mt][1], rm1);
            float cr0 = __expf(m[mt][0] - mn0), cr1 = __expf(m[mt][1] - mn1);
            m[mt][0] = mn0; m[mt][1] = mn1;

            float sum0 = 0.f, sum1 = 0.f;
#pragma unroll
            for (int nt = 0; nt < 8; nt++) {
                s[mt][nt][0] = __expf(s[mt][nt][0] - mn0);
                s[mt][nt][1] = __expf(s[mt][nt][1] - mn0);
                s[mt][nt][2] = __expf(s[mt][nt][2] - mn1);
                s[mt][nt][3] = __expf(s[mt][nt][3] - mn1);
                sum0 += s[mt][nt][0] + s[mt][nt][1];
                sum1 += s[mt][nt][2] + s[mt][nt][3];
            }
            sum0 += __shfl_xor_sync(0xffffffffu, sum0, 1);
            sum0 += __shfl_xor_sync(0xffffffffu, sum0, 2);
            sum1 += __shfl_xor_sync(0xffffffffu, sum1, 1);
            sum1 += __shfl_xor_sync(0xffffffffu, sum1, 2);
            l[mt][0] = l[mt][0] * cr0 + sum0;
            l[mt][1] = l[mt][1] * cr1 + sum1;

#pragma unroll
            for (int nt = 0; nt < 8; nt++) {
                o[mt][nt][0] *= cr0; o[mt][nt][1] *= cr0;
                o[mt][nt][2] *= cr1; o[mt][nt][3] *= cr1;
            }

            int pr = mt * 16 + (lane >> 2);
            int pc = 2 * (lane & 3);
#pragma unroll
            for (int nt = 0; nt < 8; nt++) {
                uint2 lo = make_uint2(f2tf(s[mt][nt][0]), f2tf(s[mt][nt][1]));
                uint2 hi = make_uint2(f2tf(s[mt][nt][2]), f2tf(s[mt][nt][3]));
                *(uint2*)&Pw[pr * PS_STRIDE + nt * 8 + pc]       = lo;
                *(uint2*)&Pw[(pr + 8) * PS_STRIDE + nt * 8 + pc] = hi;
            }
        }
        __syncwarp();

        // GEMM2: O += P * V (B-frags shared across mt)
#pragma unroll
        for (int ks = 0; ks < 8; ks++) {
            int pq = ks * 8 + (lane & 3);
            uint32_t a[2][4];
#pragma unroll
            for (int mt = 0; mt < 2; mt++) {
                int pr = mt * 16 + (lane >> 2);
                a[mt][0] = Pw[pr * PS_STRIDE + pq];
                a[mt][1] = Pw[(pr + 8) * PS_STRIDE + pq];
                a[mt][2] = Pw[pr * PS_STRIDE + pq + 4];
                a[mt][3] = Pw[(pr + 8) * PS_STRIDE + pq + 4];
            }
            int kr = ks * 8 + (lane & 3);
#pragma unroll
            for (int nt = 0; nt < 8; nt++) {
                int vc = nt * 8 + (lane >> 2);
                uint32_t b0 = Vs[kr * VS_STRIDE + vc];
                uint32_t b1 = Vs[(kr + 4) * VS_STRIDE + vc];
                mma_tf32(o[0][nt], a[0][0], a[0][1], a[0][2], a[0][3], b0, b1);
                mma_tf32(o[1][nt], a[1][0], a[1][1], a[1][2], a[1][3], b0, b1);
            }
        }
        __syncwarp();
    }

    // finalize -> O [B,N,DMODEL]
    int b = bh >> 4, h = bh & 15;
#pragma unroll
    for (int mt = 0; mt < 2; mt++) {
        float inv0 = 1.f / l[mt][0], inv1 = 1.f / l[mt][1];
        int n0 = qb * 128 + warp * 32 + mt * 16 + (lane >> 2);
        size_t base0 = ((size_t)(b * SEQ + n0)) * DMODEL + h * HDIM;
        size_t base1 = ((size_t)(b * SEQ + n0 + 8)) * DMODEL + h * HDIM;
#pragma unroll
        for (int nt = 0; nt < 8; nt++) {
            int c = nt * 8 + 2 * (lane & 3);
            *(float2*)&O[base0 + c] = make_float2(o[mt][nt][0] * inv0, o[mt][nt][1] * inv0);
            *(float2*)&O[base1 + c] = make_float2(o[mt][nt][2] * inv1, o[mt][nt][3] * inv1);
        }
    }
}

// ---------------------------------------------------------------------------
extern "C" void kernel_launch(void* const* d_in, const int* in_sizes, int n_in,
                              void* d_out, int out_size)
{
    const float* x    = (const float*)d_in[0];
    const float* qpos = (const float*)d_in[1];
    const float* kpos = (const float*)d_in[2];
    const float* Wq = (const float*)d_in[3];
    const float* bq = (const float*)d_in[4];
    const float* Wk = (const float*)d_in[5];
    const float* bk = (const float*)d_in[6];
    const float* Wv = (const float*)d_in[7];
    const float* bv = (const float*)d_in[8];
    const float* Wo = (const float*)d_in[9];
    const float* bo = (const float*)d_in[10];
    float* out = (float*)d_out;

    float *pq, *pk, *pv, *po;
    cudaGetSymbolAddress((void**)&pq, g_q);
    cudaGetSymbolAddress((void**)&pk, g_k);
    cudaGetSymbolAddress((void**)&pv, g_v);
    cudaGetSymbolAddress((void**)&po, g_o);

    cudaFuncSetAttribute(attn_tf32_kernel,
                         cudaFuncAttributeMaxDynamicSharedMemorySize, ATTN_SMEM);

    // fused QKV projection (+rope on q,k) -> [B,H,N,D]
    GemmArgs qkv;
    qkv.A = x;
    qkv.W[0] = Wq;  qkv.W[1] = Wk;  qkv.W[2] = Wv;
    qkv.bias[0] = bq; qkv.bias[1] = bk; qkv.bias[2] = bv;
    qkv.C[0] = pq;  qkv.C[1] = pk;  qkv.C[2] = pv;
    qkv.pos[0] = qpos; qkv.pos[1] = kpos; qkv.pos[2] = nullptr;
    qkv.layout_bhnd = 1;
    gemm_tf32_kernel<<<dim3(24, 32), 256>>>(qkv);

    // attention
    attn_tf32_kernel<<<BATCH * NHEADS * (SEQ / 128), 128, ATTN_SMEM>>>(pq, pk, pv, po);

    // output projection
    GemmArgs op;
    op.A = po;
    op.W[0] = Wo;  op.W[1] = Wo;  op.W[2] = Wo;
    op.bias[0] = bo; op.bias[1] = bo; op.bias[2] = bo;
    op.C[0] = out; op.C[1] = out; op.C[2] = out;
    op.pos[0] = nullptr; op.pos[1] = nullptr; op.pos[2] = nullptr;
    op.layout_bhnd = 0;
    gemm_tf32_kernel<<<dim3(8, 32), 256>>>(op);
}

// round 7
// speedup vs baseline: 1.2952x; 1.2952x over previous
#include <cuda_runtime.h>
#include <math.h>
#include <stdint.h>

#define BATCH   2
#define SEQ     2048
#define DMODEL  1024
#define NHEADS  16
#define HDIM    64
#define M_ROWS  (BATCH*SEQ)
#define ROPE_SCALE 0.006135923151542565f      // 2*pi/1024
#define LOG2_1E4_OVER16 0.830482023721841f    // log2(10000)/16

// Scratch (device globals: allocation-free)
__device__ float g_q[BATCH*NHEADS*SEQ*HDIM];   // [B,H,N,D] tf32-rounded, pre-scaled 1/8
__device__ float g_k[BATCH*NHEADS*SEQ*HDIM];   // tf32-rounded
__device__ float g_v[BATCH*NHEADS*SEQ*HDIM];   // tf32-rounded
__device__ float g_o[BATCH*SEQ*DMODEL];        // tf32-rounded
__device__ uint32_t g_xt[M_ROWS*DMODEL];       // x as rna-tf32
__device__ uint32_t g_wt[4*DMODEL*DMODEL];     // Wq,Wk,Wv,Wo as rna-tf32

// ---------------------------------------------------------------------------
// helpers
// ---------------------------------------------------------------------------
__device__ __forceinline__ uint32_t f2tf(float x) {
    uint32_t u;
    asm("cvt.rna.tf32.f32 %0, %1;" : "=r"(u) : "f"(x));
    return u;
}
__device__ __forceinline__ float fast_exp2(float x) {
    float y;
    asm("ex2.approx.f32 %0, %1;" : "=f"(y) : "f"(x));
    return y;
}
__device__ __forceinline__ uint32_t smem_u32(const void* p) {
    uint32_t a;
    asm("{ .reg .u64 t; cvta.to.shared.u64 t, %1; cvt.u32.u64 %0, t; }"
        : "=r"(a) : "l"(p));
    return a;
}
__device__ __forceinline__ void cp_async16(uint32_t dst, const void* src) {
    asm volatile("cp.async.cg.shared.global [%0], [%1], 16;" :: "r"(dst), "l"(src));
}
#define CP_COMMIT()  asm volatile("cp.async.commit_group;" ::: "memory")
#define CP_WAIT_1()  asm volatile("cp.async.wait_group 1;" ::: "memory")
#define CP_WAIT_0()  asm volatile("cp.async.wait_group 0;" ::: "memory")

__device__ __forceinline__ uint32_t lds32(const uint8_t* base, uint32_t off) {
    return *(const uint32_t*)(base + off);
}

__device__ __forceinline__ void mma_tf32(float c[4],
        uint32_t a0, uint32_t a1, uint32_t a2, uint32_t a3,
        uint32_t b0, uint32_t b1)
{
    asm volatile(
        "mma.sync.aligned.m16n8k8.row.col.f32.tf32.tf32.f32 "
        "{%0,%1,%2,%3}, {%4,%5,%6,%7}, {%8,%9}, {%0,%1,%2,%3};\n"
        : "+f"(c[0]), "+f"(c[1]), "+f"(c[2]), "+f"(c[3])
        : "r"(a0), "r"(a1), "r"(a2), "r"(a3), "r"(b0), "r"(b1));
}

// ---------------------------------------------------------------------------
// tf32 pre-convert (rna)
// ---------------------------------------------------------------------------
__global__ void cvt_kernel(const float4* __restrict__ src, uint4* __restrict__ dst, int n4)
{
    int i = blockIdx.x * blockDim.x + threadIdx.x;
    if (i < n4) {
        float4 v = src[i];
        dst[i] = make_uint4(f2tf(v.x), f2tf(v.y), f2tf(v.z), f2tf(v.w));
    }
}

// ---------------------------------------------------------------------------
// mma.sync tf32 GEMM with cp.async: C = A[M][1024] * W[N][1024]^T + bias (+rope)
// 256 threads, 8 warps (2M x 4N), CTA 128x128, BK=32, warp tile 64x32, 2 stages.
// smem per tile: rows of 128B (32 tf32 words), chunk swizzle c ^ (r&7).
// ---------------------------------------------------------------------------
struct GemmArgs {
    const uint32_t* A;
    const uint32_t* W[3];
    const float*    bias[3];
    float*          C[3];
    const float*    pos[3];
    int layout_bhnd;       // 1: scatter [B,H,N,D] + round(+rope); 0: row-major fp32
};

#define G_STG 32768            // A 16KB + B 16KB per stage
#define GEMM_SMEM (2*G_STG)

__global__ __launch_bounds__(256, 2)
void gemm_mma_kernel(GemmArgs args)
{
    extern __shared__ __align__(128) uint8_t smem[];
    const uint32_t sb = smem_u32(smem);

    const int tid  = threadIdx.x;
    const int warp = tid >> 5;
    const int lane = tid & 31;
    const int wm = (warp & 1) * 64;
    const int wn = (warp >> 1) * 32;
    const int proj = blockIdx.x >> 3;
    const int bn   = (blockIdx.x & 7) * 128;
    const int bm   = blockIdx.y * 128;

    const uint32_t* A    = args.A;
    const uint32_t* W    = args.W[proj];
    const float*    bias = args.bias[proj];
    float*          C    = args.C[proj];
    const float*    pos  = args.pos[proj];

    // cp.async mapping: thread -> (rows r+32i, 16B chunk c)
    const int cc = tid & 7;
    const int cr = tid >> 3;            // 0..31
    const uint32_t* gA = A + (size_t)(bm + cr) * DMODEL + cc * 4;
    const uint32_t* gB = W + (size_t)(bn + cr) * DMODEL + cc * 4;
    uint32_t cdst[4];
#pragma unroll
    for (int i = 0; i < 4; i++) {
        int R = cr + 32 * i;
        cdst[i] = R * 128 + ((cc ^ (R & 7)) << 4);
    }

#define GEMM_COPY(tile, stage) do { \
    uint32_t _sA = sb + (stage) * G_STG; \
    uint32_t _sB = _sA + 16384; \
    const uint32_t* _ga = gA + (size_t)(tile) * 32; \
    const uint32_t* _gb = gB + (size_t)(tile) * 32; \
    _Pragma("unroll") \
    for (int i = 0; i < 4; i++) { \
        cp_async16(_sA + cdst[i], _ga + (size_t)i * 32 * DMODEL); \
        cp_async16(_sB + cdst[i], _gb + (size_t)i * 32 * DMODEL); \
    } \
} while (0)

    float acc[4][4][4];
#pragma unroll
    for (int mt = 0; mt < 4; mt++)
#pragma unroll
        for (int nt = 0; nt < 4; nt++)
#pragma unroll
            for (int r = 0; r < 4; r++) acc[mt][nt][r] = 0.f;

    GEMM_COPY(0, 0); CP_COMMIT();
    GEMM_COPY(1, 1); CP_COMMIT();

    const int q = lane & 3;
    const int s = lane >> 2;

#pragma unroll 1
    for (int k0 = 0; k0 < 32; k0++) {
        if (k0 < 31) CP_WAIT_1(); else CP_WAIT_0();
        __syncthreads();

        const uint32_t soff  = (k0 & 1) * G_STG;
        const uint32_t boff0 = soff + 16384;

#pragma unroll
        for (int kbi = 0; kbi < 4; kbi++) {
            const uint32_t kx = ((2 * kbi) ^ s) << 4;
            uint32_t af[4][4];
#pragma unroll
            for (int mt = 0; mt < 4; mt++) {
                uint32_t base = soff + (wm + mt * 16 + s) * 128 + kx + q * 4;
                af[mt][0] = lds32(smem, base);
                af[mt][1] = lds32(smem, base + 1024);
                af[mt][2] = lds32(smem, base ^ 16);
                af[mt][3] = lds32(smem, (base ^ 16) + 1024);
            }
            uint32_t bf[4][2];
#pragma unroll
            for (int nt = 0; nt < 4; nt++) {
                uint32_t base = boff0 + (wn + nt * 8 + s) * 128 + kx + q * 4;
                bf[nt][0] = lds32(smem, base);
                bf[nt][1] = lds32(smem, base ^ 16);
            }
#pragma unroll
            for (int nt = 0; nt < 4; nt++)
#pragma unroll
                for (int mt = 0; mt < 4; mt++)
                    mma_tf32(acc[mt][nt], af[mt][0], af[mt][1], af[mt][2], af[mt][3],
                             bf[nt][0], bf[nt][1]);
        }
        __syncthreads();
        if (k0 + 2 < 32) { GEMM_COPY(k0 + 2, k0 & 1); CP_COMMIT(); }
    }

    // epilogue: bias (+rope, +tf32 rounding, +layout scatter)
    const float scl = (proj == 0 && args.layout_bhnd) ? 0.125f : 1.0f;
#pragma unroll
    for (int nt = 0; nt < 4; nt++) {
        int cg = bn + wn + nt * 8 + 2 * (lane & 3);
        float bv0 = bias[cg], bv1 = bias[cg + 1];
        int dd = cg & 63;
        int hh = (cg >> 6) & (NHEADS - 1);
        int ip = (dd & 31) >> 1;
        int plane = (dd >> 5) & 1;
        float invf = fast_exp2(-LOG2_1E4_OVER16 * (float)ip) * ROPE_SCALE;
#pragma unroll
        for (int mt = 0; mt < 4; mt++) {
            int r0 = bm + wm + mt * 16 + (lane >> 2);
#pragma unroll
            for (int rr = 0; rr < 2; rr++) {
                int r = r0 + rr * 8;
                float v0 = acc[mt][nt][rr * 2 + 0] + bv0;
                float v1 = acc[mt][nt][rr * 2 + 1] + bv1;
                if (args.layout_bhnd) {
                    int b = r >> 11, n = r & 2047;
                    if (pos) {
                        float ang = pos[((size_t)(b * SEQ + n)) * 2 + plane] * invf;
                        float sn, cs;
                        __sincosf(ang, &sn, &cs);
                        float y0 = v0 * cs - v1 * sn;
                        float y1 = v0 * sn + v1 * cs;
                        v0 = y0; v1 = y1;
                    }
                    v0 = __uint_as_float(f2tf(v0 * scl));
                    v1 = __uint_as_float(f2tf(v1 * scl));
                    size_t base = (((size_t)(b * NHEADS + hh)) * SEQ + n) * HDIM + dd;
                    C[base] = v0; C[base + 1] = v1;
                } else {
                    *(float2*)&C[(size_t)r * DMODEL + cg] = make_float2(v0, v1);
                }
            }
        }
    }
}

// ---------------------------------------------------------------------------
// Flash attention, mma.sync tf32, cp.async K/V: 128 q-rows/CTA, 4 warps (mt=2).
// K tile [64 key][64 dim], swizzle c^(r&7); V tile same rows, swizzle c^((r&3)<<1)
// (conflict-free for the transposed B-fragment access). Q pre-scaled+rounded.
// ---------------------------------------------------------------------------
#define AKV_STG 32768              // K 16KB + V 16KB per stage
#define PS_STRIDE 68
#define ATTN_P_OFF (2*AKV_STG)
#define ATTN_SMEM (ATTN_P_OFF + 4*32*PS_STRIDE*4)

__global__ __launch_bounds__(128)
void attn_tf32_kernel(const uint32_t* __restrict__ Q, const float* __restrict__ Kg,
                      const float* __restrict__ Vg, float* __restrict__ O)
{
    extern __shared__ __align__(128) uint8_t smem[];
    const uint32_t sb = smem_u32(smem);
    uint32_t* Pw = (uint32_t*)(smem + ATTN_P_OFF) + (threadIdx.x >> 5) * 32 * PS_STRIDE;

    const int tid  = threadIdx.x;
    const int warp = tid >> 5;
    const int lane = tid & 31;
    const int qb = blockIdx.x & 15;
    const int bh = blockIdx.x >> 4;

    // Q fragments (already *0.125 and tf32-rounded)
    const uint32_t* qbase = Q + ((size_t)bh * SEQ + qb * 128) * HDIM;
    const int q = lane & 3;
    const int s = lane >> 2;
    uint32_t qf[2][8][4];
#pragma unroll
    for (int mt = 0; mt < 2; mt++) {
        int r = warp * 32 + mt * 16 + s;
#pragma unroll
        for (int ks = 0; ks < 8; ks++) {
            int c0 = ks * 8 + q;
            qf[mt][ks][0] = qbase[(size_t)r * HDIM + c0];
            qf[mt][ks][1] = qbase[(size_t)(r + 8) * HDIM + c0];
            qf[mt][ks][2] = qbase[(size_t)r * HDIM + c0 + 4];
            qf[mt][ks][3] = qbase[(size_t)(r + 8) * HDIM + c0 + 4];
        }
    }

    float m[2][2], l[2][2];
    float o[2][8][4];
#pragma unroll
    for (int mt = 0; mt < 2; mt++) {
        m[mt][0] = -1e30f; m[mt][1] = -1e30f;
        l[mt][0] = 0.f;    l[mt][1] = 0.f;
#pragma unroll
        for (int nt = 0; nt < 8; nt++)
#pragma unroll
            for (int rr = 0; rr < 4; rr++) o[mt][nt][rr] = 0.f;
    }

    const float* kbp = Kg + (size_t)bh * SEQ * HDIM;
    const float* vbp = Vg + (size_t)bh * SEQ * HDIM;

    // cp.async mapping: thread -> (rows r8+8i, chunk cc of 16)
    const int cc = tid & 15;
    const int r8 = tid >> 4;

#define ATTN_COPY(kt, stage) do { \
    uint32_t _sK = sb + (stage) * AKV_STG; \
    uint32_t _sV = _sK + 16384; \
    _Pragma("unroll") \
    for (int i = 0; i < 8; i++) { \
        int R = r8 + 8 * i; \
        cp_async16(_sK + R * 256 + ((cc ^ (R & 7)) << 4), \
                   kbp + (size_t)((kt) + R) * HDIM + cc * 4); \
        cp_async16(_sV + R * 256 + ((cc ^ ((R & 3) << 1)) << 4), \
                   vbp + (size_t)((kt) + R) * HDIM + cc * 4); \
    } \
} while (0)

    ATTN_COPY(0, 0);  CP_COMMIT();
    ATTN_COPY(64, 1); CP_COMMIT();

#pragma unroll 1
    for (int t = 0; t < 32; t++) {
        if (t < 31) CP_WAIT_1(); else CP_WAIT_0();
        __syncthreads();

        const uint32_t koff = (t & 1) * AKV_STG;
        const uint32_t voff = koff + 16384;

        // GEMM1: S = Q * K^T
        float sc[2][8][4];
#pragma unroll
        for (int mt = 0; mt < 2; mt++)
#pragma unroll
            for (int nt = 0; nt < 8; nt++)
#pragma unroll
                for (int rr = 0; rr < 4; rr++) sc[mt][nt][rr] = 0.f;

#pragma unroll
        for (int ks = 0; ks < 8; ks++) {
            const uint32_t kx = ((2 * ks) ^ s) << 4;
#pragma unroll
            for (int nt = 0; nt < 8; nt++) {
                uint32_t base = koff + (nt * 8 + s) * 256 + kx + q * 4;
                uint32_t b0 = lds32(smem, base);
                uint32_t b1 = lds32(smem, base ^ 16);
                mma_tf32(sc[0][nt], qf[0][ks][0], qf[0][ks][1], qf[0][ks][2], qf[0][ks][3], b0, b1);
                mma_tf32(sc[1][nt], qf[1][ks][0], qf[1][ks][1], qf[1][ks][2], qf[1][ks][3], b0, b1);
            }
        }

        // online softmax + P store
#pragma unroll
        for (int mt = 0; mt < 2; mt++) {
            float rm0 = -1e30f, rm1 = -1e30f;
#pragma unroll
            for (int nt = 0; nt < 8; nt++) {
                rm0 = fmaxf(rm0, fmaxf(sc[mt][nt][0], sc[mt][nt][1]));
                rm1 = fmaxf(rm1, fmaxf(sc[mt][nt][2], sc[mt][nt][3]));
            }
            rm0 = fmaxf(rm0, __shfl_xor_sync(0xffffffffu, rm0, 1));
            rm0 = fmaxf(rm0, __shfl_xor_sync(0xffffffffu, rm0, 2));
            rm1 = fmaxf(rm1, __shfl_xor_sync(0xffffffffu, rm1, 1));
            rm1 = fmaxf(rm1, __shfl_xor_sync(0xffffffffu, rm1, 2));

            float mn0 = fmaxf(m[mt][0], rm0), mn1 = fmaxf(m[mt][1], rm1);
            float cr0 = __expf(m[mt][0] - mn0), cr1 = __expf(m[mt][1] - mn1);
            m[mt][0] = mn0; m[mt][1] = mn1;

            float sum0 = 0.f, sum1 = 0.f;
#pragma unroll
            for (int nt = 0; nt < 8; nt++) {
                sc[mt][nt][0] = __expf(sc[mt][nt][0] - mn0);
                sc[mt][nt][1] = __expf(sc[mt][nt][1] - mn0);
                sc[mt][nt][2] = __expf(sc[mt][nt][2] - mn1);
                sc[mt][nt][3] = __expf(sc[mt][nt][3] - mn1);
                sum0 += sc[mt][nt][0] + sc[mt][nt][1];
                sum1 += sc[mt][nt][2] + sc[mt][nt][3];
            }
            sum0 += __shfl_xor_sync(0xffffffffu, sum0, 1);
            sum0 += __shfl_xor_sync(0xffffffffu, sum0, 2);
            sum1 += __shfl_xor_sync(0xffffffffu, sum1, 1);
            sum1 += __shfl_xor_sync(0xffffffffu, sum1, 2);
            l[mt][0] = l[mt][0] * cr0 + sum0;
            l[mt][1] = l[mt][1] * cr1 + sum1;

#pragma unroll
            for (int nt = 0; nt < 8; nt++) {
                o[mt][nt][0] *= cr0; o[mt][nt][1] *= cr0;
                o[mt][nt][2] *= cr1; o[mt][nt][3] *= cr1;
            }

            int pr = mt * 16 + s;
            int pc = 2 * q;
#pragma unroll
            for (int nt = 0; nt < 8; nt++) {
                uint2 lo = make_uint2(f2tf(sc[mt][nt][0]), f2tf(sc[mt][nt][1]));
                uint2 hi = make_uint2(f2tf(sc[mt][nt][2]), f2tf(sc[mt][nt][3]));
                *(uint2*)&Pw[pr * PS_STRIDE + nt * 8 + pc]       = lo;
                *(uint2*)&Pw[(pr + 8) * PS_STRIDE + nt * 8 + pc] = hi;
            }
        }
        __syncwarp();

        // GEMM2: O += P * V
#pragma unroll
        for (int ks = 0; ks < 8; ks++) {
            int pq = ks * 8 + q;
            uint32_t a[2][4];
#pragma unroll
            for (int mt = 0; mt < 2; mt++) {
                int pr = mt * 16 + s;
                a[mt][0] = Pw[pr * PS_STRIDE + pq];
                a[mt][1] = Pw[(pr + 8) * PS_STRIDE + pq];
                a[mt][2] = Pw[pr * PS_STRIDE + pq + 4];
                a[mt][3] = Pw[(pr + 8) * PS_STRIDE + pq + 4];
            }
            int kr = ks * 8 + q;
#pragma unroll
            for (int nt = 0; nt < 8; nt++) {
                int vc = nt * 8 + s;
                uint32_t base = voff + kr * 256 + (((vc >> 2) ^ ((kr & 3) << 1)) << 4)
                                + (vc & 3) * 4;
                uint32_t b0 = lds32(smem, base);
                uint32_t b1 = lds32(smem, base + 1024);   // row kr+4, same swizzle sel
                mma_tf32(o[0][nt], a[0][0], a[0][1], a[0][2], a[0][3], b0, b1);
                mma_tf32(o[1][nt], a[1][0], a[1][1], a[1][2], a[1][3], b0, b1);
            }
        }
        __syncthreads();
        if (t + 2 < 32) { ATTN_COPY((t + 2) * 64, t & 1); CP_COMMIT(); }
    }

    // finalize -> O [B,N,DMODEL], tf32-rounded for the O-projection
    int b = bh >> 4, h = bh & 15;
#pragma unroll
    for (int mt = 0; mt < 2; mt++) {
        float inv0 = 1.f / l[mt][0], inv1 = 1.f / l[mt][1];
        int n0 = qb * 128 + warp * 32 + mt * 16 + s;
        size_t base0 = ((size_t)(b * SEQ + n0)) * DMODEL + h * HDIM;
        size_t base1 = ((size_t)(b * SEQ + n0 + 8)) * DMODEL + h * HDIM;
#pragma unroll
        for (int nt = 0; nt < 8; nt++) {
            int c0 = nt * 8 + 2 * q;
            *(float2*)&O[base0 + c0] = make_float2(
                __uint_as_float(f2tf(o[mt][nt][0] * inv0)),
                __uint_as_float(f2tf(o[mt][nt][1] * inv0)));
            *(float2*)&O[base1 + c0] = make_float2(
                __uint_as_float(f2tf(o[mt][nt][2] * inv1)),
                __uint_as_float(f2tf(o[mt][nt][3] * inv1)));
        }
    }
}

// ---------------------------------------------------------------------------
extern "C" void kernel_launch(void* const* d_in, const int* in_sizes, int n_in,
                              void* d_out, int out_size)
{
    const float* x    = (const float*)d_in[0];
    const float* qpos = (const float*)d_in[1];
    const float* kpos = (const float*)d_in[2];
    const float* Wq = (const float*)d_in[3];
    const float* bq = (const float*)d_in[4];
    const float* Wk = (const float*)d_in[5];
    const float* bk = (const float*)d_in[6];
    const float* Wv = (const float*)d_in[7];
    const float* bv = (const float*)d_in[8];
    const float* Wo = (const float*)d_in[9];
    const float* bo = (const float*)d_in[10];
    float* out = (float*)d_out;

    float *pq, *pk, *pv, *po;
    uint32_t *pxt, *pwt;
    cudaGetSymbolAddress((void**)&pq, g_q);
    cudaGetSymbolAddress((void**)&pk, g_k);
    cudaGetSymbolAddress((void**)&pv, g_v);
    cudaGetSymbolAddress((void**)&po, g_o);
    cudaGetSymbolAddress((void**)&pxt, g_xt);
    cudaGetSymbolAddress((void**)&pwt, g_wt);

    cudaFuncSetAttribute(gemm_mma_kernel,
                         cudaFuncAttributeMaxDynamicSharedMemorySize, GEMM_SMEM);
    cudaFuncSetAttribute(attn_tf32_kernel,
                         cudaFuncAttributeMaxDynamicSharedMemorySize, ATTN_SMEM);

    // pre-convert x + weights to rna-tf32
    const int NX4 = M_ROWS * DMODEL / 4;
    const int NW4 = DMODEL * DMODEL / 4;
    cvt_kernel<<<NX4 / 256, 256>>>((const float4*)x, (uint4*)pxt, NX4);
    cvt_kernel<<<NW4 / 256, 256>>>((const float4*)Wq, (uint4*)(pwt + 0 * DMODEL * DMODEL), NW4);
    cvt_kernel<<<NW4 / 256, 256>>>((const float4*)Wk, (uint4*)(pwt + 1 * DMODEL * DMODEL), NW4);
    cvt_kernel<<<NW4 / 256, 256>>>((const float4*)Wv, (uint4*)(pwt + 2 * DMODEL * DMODEL), NW4);
    cvt_kernel<<<NW4 / 256, 256>>>((const float4*)Wo, (uint4*)(pwt + 3 * DMODEL * DMODEL), NW4);

    // fused QKV projection (+rope on q,k; q pre-scaled; outputs tf32-rounded)
    GemmArgs qkv;
    qkv.A = pxt;
    qkv.W[0] = pwt; qkv.W[1] = pwt + DMODEL * DMODEL; qkv.W[2] = pwt + 2 * DMODEL * DMODEL;
    qkv.bias[0] = bq; qkv.bias[1] = bk; qkv.bias[2] = bv;
    qkv.C[0] = pq; qkv.C[1] = pk; qkv.C[2] = pv;
    qkv.pos[0] = qpos; qkv.pos[1] = kpos; qkv.pos[2] = nullptr;
    qkv.layout_bhnd = 1;
    gemm_mma_kernel<<<dim3(24, 32), 256, GEMM_SMEM>>>(qkv);

    // attention
    attn_tf32_kernel<<<BATCH * NHEADS * (SEQ / 128), 128, ATTN_SMEM>>>(
        (const uint32_t*)pq, pk, pv, po);

    // output projection
    GemmArgs op;
    op.A = (const uint32_t*)po;
    op.W[0] = op.W[1] = op.W[2] = pwt + 3 * DMODEL * DMODEL;
    op.bias[0] = op.bias[1] = op.bias[2] = bo;
    op.C[0] = op.C[1] = op.C[2] = out;
    op.pos[0] = op.pos[1] = op.pos[2] = nullptr;
    op.layout_bhnd = 0;
    gemm_mma_kernel<<<dim3(8, 32), 256, GEMM_SMEM>>>(op);
}

// round 8
// speedup vs baseline: 2.2766x; 1.7578x over previous
#include <cuda_runtime.h>
#include <cuda_fp16.h>
#include <math.h>
#include <stdint.h>

#define BATCH   2
#define SEQ     2048
#define DMODEL  1024
#define NHEADS  16
#define HDIM    64
#define M_ROWS  (BATCH*SEQ)
#define ROPE_SCALE 0.006135923151542565f      // 2*pi/1024
#define LOG2_1E4_OVER16 0.830482023721841f    // log2(10000)/16

// Scratch (device globals: allocation-free)
__device__ __half g_q[BATCH*NHEADS*SEQ*HDIM];   // [B,H,N,D] fp16, pre-scaled 1/8, roped
__device__ __half g_k[BATCH*NHEADS*SEQ*HDIM];   // [B,H,N,D] fp16, roped
__device__ __half g_v[BATCH*NHEADS*HDIM*SEQ];   // [B,H,D,N] fp16 TRANSPOSED
__device__ __half g_o[BATCH*SEQ*DMODEL];        // [B,N,d] fp16
__device__ __half g_xh[M_ROWS*DMODEL];          // x as fp16
__device__ __half g_wh[4*DMODEL*DMODEL];        // Wq,Wk,Wv,Wo as fp16

// ---------------------------------------------------------------------------
// helpers
// ---------------------------------------------------------------------------
__device__ __forceinline__ float fast_exp2(float x) {
    float y;
    asm("ex2.approx.f32 %0, %1;" : "=f"(y) : "f"(x));
    return y;
}
__device__ __forceinline__ uint32_t smem_u32(const void* p) {
    uint32_t a;
    asm("{ .reg .u64 t; cvta.to.shared.u64 t, %1; cvt.u32.u64 %0, t; }"
        : "=r"(a) : "l"(p));
    return a;
}
__device__ __forceinline__ void cp_async16(uint32_t dst, const void* src) {
    asm volatile("cp.async.cg.shared.global [%0], [%1], 16;" :: "r"(dst), "l"(src));
}
#define CP_COMMIT()  asm volatile("cp.async.commit_group;" ::: "memory")
#define CP_WAIT_1()  asm volatile("cp.async.wait_group 1;" ::: "memory")
#define CP_WAIT_0()  asm volatile("cp.async.wait_group 0;" ::: "memory")

__device__ __forceinline__ uint32_t lds32(const uint8_t* base, uint32_t off) {
    return *(const uint32_t*)(base + off);
}
__device__ __forceinline__ uint32_t pack_h2(float a, float b) {
    __half2 h = __floats2half2_rn(a, b);
    return *(uint32_t*)&h;
}

// m16n8k16 fp16 MMA, fp32 accumulate
__device__ __forceinline__ void mma_f16(float c[4], const uint32_t a[4],
                                        uint32_t b0, uint32_t b1)
{
    asm volatile(
        "mma.sync.aligned.m16n8k16.row.col.f32.f16.f16.f32 "
        "{%0,%1,%2,%3}, {%4,%5,%6,%7}, {%8,%9}, {%0,%1,%2,%3};\n"
        : "+f"(c[0]), "+f"(c[1]), "+f"(c[2]), "+f"(c[3])
        : "r"(a[0]), "r"(a[1]), "r"(a[2]), "r"(a[3]), "r"(b0), "r"(b1));
}

// ---------------------------------------------------------------------------
// fp16 pre-convert (rn)
// ---------------------------------------------------------------------------
__global__ void cvt_kernel(const float4* __restrict__ src, uint2* __restrict__ dst, int n4)
{
    int i = blockIdx.x * blockDim.x + threadIdx.x;
    if (i < n4) {
        float4 v = src[i];
        dst[i] = make_uint2(pack_h2(v.x, v.y), pack_h2(v.z, v.w));
    }
}

// ---------------------------------------------------------------------------
// fp16 mma GEMM with cp.async: C = A[M][1024] * W[N][1024]^T + bias (+rope)
// 256 threads, 8 warps (2M x 4N), CTA 128x128, BK=64 halves (128B rows),
// warp tile 64x32, 2 stages, chunk swizzle c ^ (r&7).
// ---------------------------------------------------------------------------
struct GemmArgs {
    const __half* A;
    const __half* W[3];
    const float*  bias[3];
    void*         C[3];
    const float*  pos[3];
    int layout_bhnd;   // 1: scatter half [B,H,N,D] (+rope; proj2 -> transposed V); 0: fp32 [M][1024]
};

#define G_STG 32768            // A 16KB + B 16KB per stage
#define GEMM_SMEM (2*G_STG)

__global__ __launch_bounds__(256, 2)
void gemm_mma_kernel(GemmArgs args)
{
    extern __shared__ __align__(128) uint8_t smem[];
    const uint32_t sb = smem_u32(smem);

    const int tid  = threadIdx.x;
    const int warp = tid >> 5;
    const int lane = tid & 31;
    const int wm = (warp & 1) * 64;
    const int wn = (warp >> 1) * 32;
    const int proj = blockIdx.x >> 3;
    const int bn   = (blockIdx.x & 7) * 128;
    const int bm   = blockIdx.y * 128;

    const __half* A    = args.A;
    const __half* W    = args.W[proj];
    const float*  bias = args.bias[proj];
    const float*  pos  = args.pos[proj];

    // cp.async mapping: thread -> (rows r+32i, 16B chunk cc = 8 halves)
    const int cc = tid & 7;
    const int cr = tid >> 3;            // 0..31
    const __half* gA = A + (size_t)(bm + cr) * DMODEL + cc * 8;
    const __half* gB = W + (size_t)(bn + cr) * DMODEL + cc * 8;
    uint32_t cdst[4];
#pragma unroll
    for (int i = 0; i < 4; i++) {
        int R = cr + 32 * i;
        cdst[i] = R * 128 + ((cc ^ (R & 7)) << 4);
    }

#define GEMM_COPY(tile, stage) do { \
    uint32_t _sA = sb + (stage) * G_STG; \
    uint32_t _sB = _sA + 16384; \
    const __half* _ga = gA + (size_t)(tile) * 64; \
    const __half* _gb = gB + (size_t)(tile) * 64; \
    _Pragma("unroll") \
    for (int i = 0; i < 4; i++) { \
        cp_async16(_sA + cdst[i], _ga + (size_t)i * 32 * DMODEL); \
        cp_async16(_sB + cdst[i], _gb + (size_t)i * 32 * DMODEL); \
    } \
} while (0)

    float acc[4][4][4];
#pragma unroll
    for (int mt = 0; mt < 4; mt++)
#pragma unroll
        for (int nt = 0; nt < 4; nt++)
#pragma unroll
            for (int r = 0; r < 4; r++) acc[mt][nt][r] = 0.f;

    GEMM_COPY(0, 0); CP_COMMIT();
    GEMM_COPY(1, 1); CP_COMMIT();

    const int q = lane & 3;
    const int s = lane >> 2;

#pragma unroll 1
    for (int k0 = 0; k0 < 16; k0++) {
        if (k0 < 15) CP_WAIT_1(); else CP_WAIT_0();
        __syncthreads();

        const uint32_t soff  = (k0 & 1) * G_STG;
        const uint32_t boff0 = soff + 16384;

#pragma unroll
        for (int kbi = 0; kbi < 4; kbi++) {
            const uint32_t kx = ((2 * kbi) ^ s) << 4;
            uint32_t af[4][4];
#pragma unroll
            for (int mt = 0; mt < 4; mt++) {
                uint32_t base = soff + (wm + mt * 16 + s) * 128 + kx + q * 4;
                af[mt][0] = lds32(smem, base);
                af[mt][1] = lds32(smem, base + 1024);
                af[mt][2] = lds32(smem, base ^ 16);
                af[mt][3] = lds32(smem, (base ^ 16) + 1024);
            }
#pragma unroll
            for (int nt = 0; nt < 4; nt++) {
                uint32_t base = boff0 + (wn + nt * 8 + s) * 128 + kx + q * 4;
                uint32_t b0 = lds32(smem, base);
                uint32_t b1 = lds32(smem, base ^ 16);
#pragma unroll
                for (int mt = 0; mt < 4; mt++)
                    mma_f16(acc[mt][nt], af[mt], b0, b1);
            }
        }
        __syncthreads();
        if (k0 + 2 < 16) { GEMM_COPY(k0 + 2, k0 & 1); CP_COMMIT(); }
    }

    // epilogue
    const float scl = (proj == 0 && args.layout_bhnd) ? 0.125f : 1.0f;
#pragma unroll
    for (int nt = 0; nt < 4; nt++) {
        int cg = bn + wn + nt * 8 + 2 * q;
        float bv0 = bias[cg], bv1 = bias[cg + 1];
        int dd = cg & 63;
        int hh = (cg >> 6) & (NHEADS - 1);
        int ip = (dd & 31) >> 1;
        int plane = (dd >> 5) & 1;
        float invf = fast_exp2(-LOG2_1E4_OVER16 * (float)ip) * ROPE_SCALE;
#pragma unroll
        for (int mt = 0; mt < 4; mt++) {
            int r0 = bm + wm + mt * 16 + s;
#pragma unroll
            for (int rr = 0; rr < 2; rr++) {
                int r = r0 + rr * 8;
                float v0 = acc[mt][nt][rr * 2 + 0] + bv0;
                float v1 = acc[mt][nt][rr * 2 + 1] + bv1;
                if (args.layout_bhnd) {
                    int b = r >> 11, n = r & 2047;
                    if (pos) {
                        float ang = pos[((size_t)(b * SEQ + n)) * 2 + plane] * invf;
                        float sn, cs;
                        __sincosf(ang, &sn, &cs);
                        float y0 = v0 * cs - v1 * sn;
                        float y1 = v0 * sn + v1 * cs;
                        v0 = y0; v1 = y1;
                    }
                    __half* Ch = (__half*)args.C[proj];
                    if (proj == 2) {
                        // V transposed: [B,H,D,N]
                        size_t tb = ((size_t)(b * NHEADS + hh) * HDIM + dd) * SEQ + n;
                        Ch[tb]       = __float2half_rn(v0);
                        Ch[tb + SEQ] = __float2half_rn(v1);
                    } else {
                        size_t base = (((size_t)(b * NHEADS + hh)) * SEQ + n) * HDIM + dd;
                        *(uint32_t*)&Ch[base] = pack_h2(v0 * scl, v1 * scl);
                    }
                } else {
                    float* Cf = (float*)args.C[proj];
                    *(float2*)&Cf[(size_t)r * DMODEL + cg] = make_float2(v0, v1);
                }
            }
        }
    }
}

// ---------------------------------------------------------------------------
// Flash attention, fp16 mma k16: 128 q-rows/CTA, 4 warps (warp tile 32x64).
// K tile [key64][dim64] fp16 (128B rows); V tile TRANSPOSED [dim64][key64].
// Both swizzle c^(r&7). P per-warp fp16 (32 x 64 halves, stride 36 words).
// ---------------------------------------------------------------------------
#define AKV_STG 16384              // K 8KB + V 8KB per stage
#define PS_W 36                    // P row stride in words
#define ATTN_P_OFF (2*AKV_STG)
#define ATTN_SMEM (ATTN_P_OFF + 4*32*PS_W*4)

__global__ __launch_bounds__(128)
void attn_f16_kernel(const __half* __restrict__ Q, const __half* __restrict__ Kg,
                     const __half* __restrict__ Vg, __half* __restrict__ O)
{
    extern __shared__ __align__(128) uint8_t smem[];
    const uint32_t sb = smem_u32(smem);
    uint32_t* Pw = (uint32_t*)(smem + ATTN_P_OFF) + (threadIdx.x >> 5) * 32 * PS_W;

    const int tid  = threadIdx.x;
    const int warp = tid >> 5;
    const int lane = tid & 31;
    const int qb = blockIdx.x & 15;
    const int bh = blockIdx.x >> 4;

    const int q = lane & 3;
    const int s = lane >> 2;

    // Q fragments (pre-scaled, fp16): rows warp*32+mt*16+s(+8), 4 k-steps of 16
    const uint32_t* qw = (const uint32_t*)(Q + ((size_t)bh * SEQ + qb * 128) * HDIM);
    uint32_t qf[2][4][4];
#pragma unroll
    for (int mt = 0; mt < 2; mt++) {
        int r = warp * 32 + mt * 16 + s;
#pragma unroll
        for (int ks = 0; ks < 4; ks++) {
            qf[mt][ks][0] = qw[(size_t)r * 32 + ks * 8 + q];
            qf[mt][ks][1] = qw[(size_t)(r + 8) * 32 + ks * 8 + q];
            qf[mt][ks][2] = qw[(size_t)r * 32 + ks * 8 + q + 4];
            qf[mt][ks][3] = qw[(size_t)(r + 8) * 32 + ks * 8 + q + 4];
        }
    }

    float m[2][2], l[2][2];
    float o[2][8][4];
#pragma unroll
    for (int mt = 0; mt < 2; mt++) {
        m[mt][0] = -1e30f; m[mt][1] = -1e30f;
        l[mt][0] = 0.f;    l[mt][1] = 0.f;
#pragma unroll
        for (int nt = 0; nt < 8; nt++)
#pragma unroll
            for (int rr = 0; rr < 4; rr++) o[mt][nt][rr] = 0.f;
    }

    const __half* kbp = Kg + (size_t)bh * SEQ * HDIM;            // [key][dim]
    const __half* vbp = Vg + (size_t)bh * HDIM * SEQ;            // [dim][key]

    // cp.async mapping: 128 thr -> rows r16+16i (i<4), chunk cc (8 halves)
    const int cc  = tid & 7;
    const int r16 = tid >> 3;      // 0..15

#define ATTN_COPY(kt, stage) do { \
    uint32_t _sK = sb + (stage) * AKV_STG; \
    uint32_t _sV = _sK + 8192; \
    _Pragma("unroll") \
    for (int i = 0; i < 4; i++) { \
        int R = r16 + 16 * i; \
        uint32_t _d = R * 128 + ((cc ^ (R & 7)) << 4); \
        cp_async16(_sK + _d, kbp + (size_t)((kt) + R) * HDIM + cc * 8); \
        cp_async16(_sV + _d, vbp + (size_t)R * SEQ + (kt) + cc * 8); \
    } \
} while (0)

    ATTN_COPY(0, 0);  CP_COMMIT();
    ATTN_COPY(64, 1); CP_COMMIT();

#pragma unroll 1
    for (int t = 0; t < 32; t++) {
        if (t < 31) CP_WAIT_1(); else CP_WAIT_0();
        __syncthreads();

        const uint32_t koff = (t & 1) * AKV_STG;
        const uint32_t voff = koff + 8192;

        // GEMM1: S = Q * K^T  (keys nt*8+s, dims 4 k-steps)
        float sc[2][8][4];
#pragma unroll
        for (int mt = 0; mt < 2; mt++)
#pragma unroll
            for (int nt = 0; nt < 8; nt++)
#pragma unroll
                for (int rr = 0; rr < 4; rr++) sc[mt][nt][rr] = 0.f;

#pragma unroll
        for (int ks = 0; ks < 4; ks++) {
            const uint32_t kx = ((2 * ks) ^ s) << 4;
#pragma unroll
            for (int nt = 0; nt < 8; nt++) {
                uint32_t base = koff + (nt * 8 + s) * 128 + kx + q * 4;
                uint32_t b0 = lds32(smem, base);
                uint32_t b1 = lds32(smem, base ^ 16);
                mma_f16(sc[0][nt], qf[0][ks], b0, b1);
                mma_f16(sc[1][nt], qf[1][ks], b0, b1);
            }
        }

        // online softmax + P store (fp16)
#pragma unroll
        for (int mt = 0; mt < 2; mt++) {
            float rm0 = -1e30f, rm1 = -1e30f;
#pragma unroll
            for (int nt = 0; nt < 8; nt++) {
                rm0 = fmaxf(rm0, fmaxf(sc[mt][nt][0], sc[mt][nt][1]));
                rm1 = fmaxf(rm1, fmaxf(sc[mt][nt][2], sc[mt][nt][3]));
            }
            rm0 = fmaxf(rm0, __shfl_xor_sync(0xffffffffu, rm0, 1));
            rm0 = fmaxf(rm0, __shfl_xor_sync(0xffffffffu, rm0, 2));
            rm1 = fmaxf(rm1, __shfl_xor_sync(0xffffffffu, rm1, 1));
            rm1 = fmaxf(rm1, __shfl_xor_sync(0xffffffffu, rm1, 2));

            float mn0 = fmaxf(m[mt][0], rm0), mn1 = fmaxf(m[mt][1], rm1);
            float cr0 = __expf(m[mt][0] - mn0), cr1 = __expf(m[mt][1] - mn1);
            m[mt][0] = mn0; m[mt][1] = mn1;

            float sum0 = 0.f, sum1 = 0.f;
#pragma unroll
            for (int nt = 0; nt < 8; nt++) {
                sc[mt][nt][0] = __expf(sc[mt][nt][0] - mn0);
                sc[mt][nt][1] = __expf(sc[mt][nt][1] - mn0);
                sc[mt][nt][2] = __expf(sc[mt][nt][2] - mn1);
                sc[mt][nt][3] = __expf(sc[mt][nt][3] - mn1);
                sum0 += sc[mt][nt][0] + sc[mt][nt][1];
                sum1 += sc[mt][nt][2] + sc[mt][nt][3];
            }
            sum0 += __shfl_xor_sync(0xffffffffu, sum0, 1);
            sum0 += __shfl_xor_sync(0xffffffffu, sum0, 2);
            sum1 += __shfl_xor_sync(0xffffffffu, sum1, 1);
            sum1 += __shfl_xor_sync(0xffffffffu, sum1, 2);
            l[mt][0] = l[mt][0] * cr0 + sum0;
            l[mt][1] = l[mt][1] * cr1 + sum1;

#pragma unroll
            for (int nt = 0; nt < 8; nt++) {
                o[mt][nt][0] *= cr0; o[mt][nt][1] *= cr0;
                o[mt][nt][2] *= cr1; o[mt][nt][3] *= cr1;
            }

            int pr = mt * 16 + s;
#pragma unroll
            for (int nt = 0; nt < 8; nt++) {
                Pw[pr * PS_W + nt * 4 + q]       = pack_h2(sc[mt][nt][0], sc[mt][nt][1]);
                Pw[(pr + 8) * PS_W + nt * 4 + q] = pack_h2(sc[mt][nt][2], sc[mt][nt][3]);
            }
        }
        __syncwarp();

        // GEMM2: O += P * V^T  (dims nt*8+s, keys 4 k-steps)
#pragma unroll
        for (int kbi = 0; kbi < 4; kbi++) {
            uint32_t a[2][4];
#pragma unroll
            for (int mt = 0; mt < 2; mt++) {
                int pr = mt * 16 + s;
                a[mt][0] = Pw[pr * PS_W + kbi * 8 + q];
                a[mt][1] = Pw[(pr + 8) * PS_W + kbi * 8 + q];
                a[mt][2] = Pw[pr * PS_W + kbi * 8 + q + 4];
                a[mt][3] = Pw[(pr + 8) * PS_W + kbi * 8 + q + 4];
            }
            const uint32_t kx = ((2 * kbi) ^ s) << 4;
#pragma unroll
            for (int nt = 0; nt < 8; nt++) {
                uint32_t base = voff + (nt * 8 + s) * 128 + kx + q * 4;
                uint32_t b0 = lds32(smem, base);
                uint32_t b1 = lds32(smem, base ^ 16);
                mma_f16(o[0][nt], a[0], b0, b1);
                mma_f16(o[1][nt], a[1], b0, b1);
            }
        }
        __syncthreads();
        if (t + 2 < 32) { ATTN_COPY((t + 2) * 64, t & 1); CP_COMMIT(); }
    }

    // finalize -> O half [B,N,DMODEL]
    int b = bh >> 4, h = bh & 15;
#pragma unroll
    for (int mt = 0; mt < 2; mt++) {
        float inv0 = 1.f / l[mt][0], inv1 = 1.f / l[mt][1];
        int n0 = qb * 128 + warp * 32 + mt * 16 + s;
        size_t base0 = ((size_t)(b * SEQ + n0)) * DMODEL + h * HDIM;
        size_t base1 = ((size_t)(b * SEQ + n0 + 8)) * DMODEL + h * HDIM;
#pragma unroll
        for (int nt = 0; nt < 8; nt++) {
            int c0 = nt * 8 + 2 * q;
            *(uint32_t*)&O[base0 + c0] = pack_h2(o[mt][nt][0] * inv0, o[mt][nt][1] * inv0);
            *(uint32_t*)&O[base1 + c0] = pack_h2(o[mt][nt][2] * inv1, o[mt][nt][3] * inv1);
        }
    }
}

// ---------------------------------------------------------------------------
extern "C" void kernel_launch(void* const* d_in, const int* in_sizes, int n_in,
                              void* d_out, int out_size)
{
    const float* x    = (const float*)d_in[0];
    const float* qpos = (const float*)d_in[1];
    const float* kpos = (const float*)d_in[2];
    const float* Wq = (const float*)d_in[3];
    const float* bq = (const float*)d_in[4];
    const float* Wk = (const float*)d_in[5];
    const float* bk = (const float*)d_in[6];
    const float* Wv = (const float*)d_in[7];
    const float* bv = (const float*)d_in[8];
    const float* Wo = (const float*)d_in[9];
    const float* bo = (const float*)d_in[10];
    float* out = (float*)d_out;

    __half *pq, *pk, *pv, *po, *pxh, *pwh;
    cudaGetSymbolAddress((void**)&pq, g_q);
    cudaGetSymbolAddress((void**)&pk, g_k);
    cudaGetSymbolAddress((void**)&pv, g_v);
    cudaGetSymbolAddress((void**)&po, g_o);
    cudaGetSymbolAddress((void**)&pxh, g_xh);
    cudaGetSymbolAddress((void**)&pwh, g_wh);

    cudaFuncSetAttribute(gemm_mma_kernel,
                         cudaFuncAttributeMaxDynamicSharedMemorySize, GEMM_SMEM);
    cudaFuncSetAttribute(attn_f16_kernel,
                         cudaFuncAttributeMaxDynamicSharedMemorySize, ATTN_SMEM);

    // pre-convert x + weights to fp16
    const int NX4 = M_ROWS * DMODEL / 4;
    const int NW4 = DMODEL * DMODEL / 4;
    cvt_kernel<<<NX4 / 256, 256>>>((const float4*)x, (uint2*)pxh, NX4);
    cvt_kernel<<<NW4 / 256, 256>>>((const float4*)Wq, (uint2*)(pwh + 0 * DMODEL * DMODEL), NW4);
    cvt_kernel<<<NW4 / 256, 256>>>((const float4*)Wk, (uint2*)(pwh + 1 * DMODEL * DMODEL), NW4);
    cvt_kernel<<<NW4 / 256, 256>>>((const float4*)Wv, (uint2*)(pwh + 2 * DMODEL * DMODEL), NW4);
    cvt_kernel<<<NW4 / 256, 256>>>((const float4*)Wo, (uint2*)(pwh + 3 * DMODEL * DMODEL), NW4);

    // fused QKV projection (+rope on q,k; q pre-scaled; V transposed)
    GemmArgs qkv;
    qkv.A = pxh;
    qkv.W[0] = pwh; qkv.W[1] = pwh + DMODEL * DMODEL; qkv.W[2] = pwh + 2 * DMODEL * DMODEL;
    qkv.bias[0] = bq; qkv.bias[1] = bk; qkv.bias[2] = bv;
    qkv.C[0] = pq; qkv.C[1] = pk; qkv.C[2] = pv;
    qkv.pos[0] = qpos; qkv.pos[1] = kpos; qkv.pos[2] = nullptr;
    qkv.layout_bhnd = 1;
    gemm_mma_kernel<<<dim3(24, 32), 256, GEMM_SMEM>>>(qkv);

    // attention
    attn_f16_kernel<<<BATCH * NHEADS * (SEQ / 128), 128, ATTN_SMEM>>>(pq, pk, pv, po);

    // output projection
    GemmArgs op;
    op.A = po;
    op.W[0] = op.W[1] = op.W[2] = pwh + 3 * DMODEL * DMODEL;
    op.bias[0] = op.bias[1] = op.bias[2] = bo;
    op.C[0] = op.C[1] = op.C[2] = out;
    op.pos[0] = op.pos[1] = op.pos[2] = nullptr;
    op.layout_bhnd = 0;
    gemm_mma_kernel<<<dim3(8, 32), 256, GEMM_SMEM>>>(op);
}

// round 9
// speedup vs baseline: 2.4222x; 1.0639x over previous
#include <cuda_runtime.h>
#include <cuda_fp16.h>
#include <math.h>
#include <stdint.h>

#define BATCH   2
#define SEQ     2048
#define DMODEL  1024
#define NHEADS  16
#define HDIM    64
#define M_ROWS  (BATCH*SEQ)
#define ROPE_SCALE 0.006135923151542565f      // 2*pi/1024
#define LOG2_1E4_OVER16 0.830482023721841f    // log2(10000)/16
#define QSCALE 0.1803368801111204f            // 0.125 * log2(e)

// Scratch (device globals: allocation-free)
__device__ __half g_q[BATCH*NHEADS*SEQ*HDIM];   // [B,H,N,D] fp16, *0.125*log2e, roped
__device__ __half g_k[BATCH*NHEADS*SEQ*HDIM];   // [B,H,N,D] fp16, roped
__device__ __half g_v[BATCH*NHEADS*HDIM*SEQ];   // [B,H,D,N] fp16 TRANSPOSED
__device__ __half g_o[BATCH*SEQ*DMODEL];        // [B,N,d] fp16
__device__ __half g_xh[M_ROWS*DMODEL];          // x as fp16
__device__ __half g_wh[4*DMODEL*DMODEL];        // Wq,Wk,Wv,Wo as fp16

// ---------------------------------------------------------------------------
// helpers
// ---------------------------------------------------------------------------
__device__ __forceinline__ float fast_exp2(float x) {
    float y;
    asm("ex2.approx.f32 %0, %1;" : "=f"(y) : "f"(x));
    return y;
}
__device__ __forceinline__ uint32_t smem_u32(const void* p) {
    uint32_t a;
    asm("{ .reg .u64 t; cvta.to.shared.u64 t, %1; cvt.u32.u64 %0, t; }"
        : "=r"(a) : "l"(p));
    return a;
}
__device__ __forceinline__ void cp_async16(uint32_t dst, const void* src) {
    asm volatile("cp.async.cg.shared.global [%0], [%1], 16;" :: "r"(dst), "l"(src));
}
#define CP_COMMIT()  asm volatile("cp.async.commit_group;" ::: "memory")
#define CP_WAIT_1()  asm volatile("cp.async.wait_group 1;" ::: "memory")
#define CP_WAIT_0()  asm volatile("cp.async.wait_group 0;" ::: "memory")

__device__ __forceinline__ uint32_t lds32(const uint8_t* base, uint32_t off) {
    return *(const uint32_t*)(base + off);
}
__device__ __forceinline__ uint32_t pack_h2(float a, float b) {
    __half2 h = __floats2half2_rn(a, b);
    return *(uint32_t*)&h;
}
__device__ __forceinline__ uint32_t h2exp2_u32(uint32_t x) {
    uint32_t y;
    asm("ex2.approx.f16x2 %0, %1;" : "=r"(y) : "r"(x));
    return y;
}
__device__ __forceinline__ __half2 u2h2(uint32_t x) { return *(__half2*)&x; }

// m16n8k16 fp16 MMA, fp32 accumulate
__device__ __forceinline__ void mma_f16(float c[4], const uint32_t a[4],
                                        uint32_t b0, uint32_t b1)
{
    asm volatile(
        "mma.sync.aligned.m16n8k16.row.col.f32.f16.f16.f32 "
        "{%0,%1,%2,%3}, {%4,%5,%6,%7}, {%8,%9}, {%0,%1,%2,%3};\n"
        : "+f"(c[0]), "+f"(c[1]), "+f"(c[2]), "+f"(c[3])
        : "r"(a[0]), "r"(a[1]), "r"(a[2]), "r"(a[3]), "r"(b0), "r"(b1));
}

// ---------------------------------------------------------------------------
// merged fp16 pre-convert: x (1M float4) then Wq,Wk,Wv,Wo (256K float4 each)
// ---------------------------------------------------------------------------
struct CvtArgs { const float4* src[5]; };
#define NX4 (M_ROWS*DMODEL/4)
#define NW4 (DMODEL*DMODEL/4)

__global__ void cvt_all_kernel(CvtArgs a, uint2* __restrict__ dstX,
                               uint2* __restrict__ dstW)
{
    int i = blockIdx.x * blockDim.x + threadIdx.x;
    float4 v;
    uint2* d;
    if (i < NX4) {
        v = a.src[0][i];
        d = dstX + i;
    } else {
        int j = i - NX4;
        v = a.src[1 + (j >> 18)][j & (NW4 - 1)];
        d = dstW + j;
    }
    *d = make_uint2(pack_h2(v.x, v.y), pack_h2(v.z, v.w));
}

// ---------------------------------------------------------------------------
// fp16 mma GEMM with cp.async (unchanged from R8): C = A*W^T + bias (+rope)
// 256 threads, 8 warps (2M x 4N), CTA 128x128, BK=64 halves, 2 stages.
// ---------------------------------------------------------------------------
struct GemmArgs {
    const __half* A;
    const __half* W[3];
    const float*  bias[3];
    void*         C[3];
    const float*  pos[3];
    int layout_bhnd;
};

#define G_STG 32768
#define GEMM_SMEM (2*G_STG)

__global__ __launch_bounds__(256, 2)
void gemm_mma_kernel(GemmArgs args)
{
    extern __shared__ __align__(128) uint8_t smem[];
    const uint32_t sb = smem_u32(smem);

    const int tid  = threadIdx.x;
    const int warp = tid >> 5;
    const int lane = tid & 31;
    const int wm = (warp & 1) * 64;
    const int wn = (warp >> 1) * 32;
    const int proj = blockIdx.x >> 3;
    const int bn   = (blockIdx.x & 7) * 128;
    const int bm   = blockIdx.y * 128;

    const __half* A    = args.A;
    const __half* W    = args.W[proj];
    const float*  bias = args.bias[proj];
    const float*  pos  = args.pos[proj];

    const int cc = tid & 7;
    const int cr = tid >> 3;
    const __half* gA = A + (size_t)(bm + cr) * DMODEL + cc * 8;
    const __half* gB = W + (size_t)(bn + cr) * DMODEL + cc * 8;
    uint32_t cdst[4];
#pragma unroll
    for (int i = 0; i < 4; i++) {
        int R = cr + 32 * i;
        cdst[i] = R * 128 + ((cc ^ (R & 7)) << 4);
    }

#define GEMM_COPY(tile, stage) do { \
    uint32_t _sA = sb + (stage) * G_STG; \
    uint32_t _sB = _sA + 16384; \
    const __half* _ga = gA + (size_t)(tile) * 64; \
    const __half* _gb = gB + (size_t)(tile) * 64; \
    _Pragma("unroll") \
    for (int i = 0; i < 4; i++) { \
        cp_async16(_sA + cdst[i], _ga + (size_t)i * 32 * DMODEL); \
        cp_async16(_sB + cdst[i], _gb + (size_t)i * 32 * DMODEL); \
    } \
} while (0)

    float acc[4][4][4];
#pragma unroll
    for (int mt = 0; mt < 4; mt++)
#pragma unroll
        for (int nt = 0; nt < 4; nt++)
#pragma unroll
            for (int r = 0; r < 4; r++) acc[mt][nt][r] = 0.f;

    GEMM_COPY(0, 0); CP_COMMIT();
    GEMM_COPY(1, 1); CP_COMMIT();

    const int q = lane & 3;
    const int s = lane >> 2;

#pragma unroll 1
    for (int k0 = 0; k0 < 16; k0++) {
        if (k0 < 15) CP_WAIT_1(); else CP_WAIT_0();
        __syncthreads();

        const uint32_t soff  = (k0 & 1) * G_STG;
        const uint32_t boff0 = soff + 16384;

#pragma unroll
        for (int kbi = 0; kbi < 4; kbi++) {
            const uint32_t kx = ((2 * kbi) ^ s) << 4;
            uint32_t af[4][4];
#pragma unroll
            for (int mt = 0; mt < 4; mt++) {
                uint32_t base = soff + (wm + mt * 16 + s) * 128 + kx + q * 4;
                af[mt][0] = lds32(smem, base);
                af[mt][1] = lds32(smem, base + 1024);
                af[mt][2] = lds32(smem, base ^ 16);
                af[mt][3] = lds32(smem, (base ^ 16) + 1024);
            }
#pragma unroll
            for (int nt = 0; nt < 4; nt++) {
                uint32_t base = boff0 + (wn + nt * 8 + s) * 128 + kx + q * 4;
                uint32_t b0 = lds32(smem, base);
                uint32_t b1 = lds32(smem, base ^ 16);
#pragma unroll
                for (int mt = 0; mt < 4; mt++)
                    mma_f16(acc[mt][nt], af[mt], b0, b1);
            }
        }
        __syncthreads();
        if (k0 + 2 < 16) { GEMM_COPY(k0 + 2, k0 & 1); CP_COMMIT(); }
    }

    // epilogue
    const float scl = (proj == 0 && args.layout_bhnd) ? QSCALE : 1.0f;
#pragma unroll
    for (int nt = 0; nt < 4; nt++) {
        int cg = bn + wn + nt * 8 + 2 * q;
        float bv0 = bias[cg], bv1 = bias[cg + 1];
        int dd = cg & 63;
        int hh = (cg >> 6) & (NHEADS - 1);
        int ip = (dd & 31) >> 1;
        int plane = (dd >> 5) & 1;
        float invf = fast_exp2(-LOG2_1E4_OVER16 * (float)ip) * ROPE_SCALE;
#pragma unroll
        for (int mt = 0; mt < 4; mt++) {
            int r0 = bm + wm + mt * 16 + s;
#pragma unroll
            for (int rr = 0; rr < 2; rr++) {
                int r = r0 + rr * 8;
                float v0 = acc[mt][nt][rr * 2 + 0] + bv0;
                float v1 = acc[mt][nt][rr * 2 + 1] + bv1;
                if (args.layout_bhnd) {
                    int b = r >> 11, n = r & 2047;
                    if (pos) {
                        float ang = pos[((size_t)(b * SEQ + n)) * 2 + plane] * invf;
                        float sn, cs;
                        __sincosf(ang, &sn, &cs);
                        float y0 = v0 * cs - v1 * sn;
                        float y1 = v0 * sn + v1 * cs;
                        v0 = y0; v1 = y1;
                    }
                    __half* Ch = (__half*)args.C[proj];
                    if (proj == 2) {
                        size_t tb = ((size_t)(b * NHEADS + hh) * HDIM + dd) * SEQ + n;
                        Ch[tb]       = __float2half_rn(v0);
                        Ch[tb + SEQ] = __float2half_rn(v1);
                    } else {
                        size_t base = (((size_t)(b * NHEADS + hh)) * SEQ + n) * HDIM + dd;
                        *(uint32_t*)&Ch[base] = pack_h2(v0 * scl, v1 * scl);
                    }
                } else {
                    float* Cf = (float*)args.C[proj];
                    *(float2*)&Cf[(size_t)r * DMODEL + cg] = make_float2(v0, v1);
                }
            }
        }
    }
}

// ---------------------------------------------------------------------------
// Flash attention, fp16 mma k16, exp2-domain f16x2 softmax, P in registers.
// 128 q-rows/CTA, 4 warps (warp tile 32x64). K [key64][dim64], V^T [dim64][key64].
// ---------------------------------------------------------------------------
#define AKV_STG 16384              // K 8KB + V 8KB per stage
#define ATTN_SMEM (2*AKV_STG)

__global__ __launch_bounds__(128)
void attn_f16_kernel(const __half* __restrict__ Q, const __half* __restrict__ Kg,
                     const __half* __restrict__ Vg, __half* __restrict__ O)
{
    extern __shared__ __align__(128) uint8_t smem[];
    const uint32_t sb = smem_u32(smem);

    const int tid  = threadIdx.x;
    const int warp = tid >> 5;
    const int lane = tid & 31;
    const int qb = blockIdx.x & 15;
    const int bh = blockIdx.x >> 4;

    const int q = lane & 3;
    const int s = lane >> 2;

    // Q fragments (pre-scaled by 0.125*log2e, fp16)
    const uint32_t* qw = (const uint32_t*)(Q + ((size_t)bh * SEQ + qb * 128) * HDIM);
    uint32_t qf[2][4][4];
#pragma unroll
    for (int mt = 0; mt < 2; mt++) {
        int r = warp * 32 + mt * 16 + s;
#pragma unroll
        for (int ks = 0; ks < 4; ks++) {
            qf[mt][ks][0] = qw[(size_t)r * 32 + ks * 8 + q];
            qf[mt][ks][1] = qw[(size_t)(r + 8) * 32 + ks * 8 + q];
            qf[mt][ks][2] = qw[(size_t)r * 32 + ks * 8 + q + 4];
            qf[mt][ks][3] = qw[(size_t)(r + 8) * 32 + ks * 8 + q + 4];
        }
    }

    float m[2][2], l[2][2];
    float o[2][8][4];
#pragma unroll
    for (int mt = 0; mt < 2; mt++) {
        m[mt][0] = -1e30f; m[mt][1] = -1e30f;
        l[mt][0] = 0.f;    l[mt][1] = 0.f;
#pragma unroll
        for (int nt = 0; nt < 8; nt++)
#pragma unroll
            for (int rr = 0; rr < 4; rr++) o[mt][nt][rr] = 0.f;
    }

    const __half* kbp = Kg + (size_t)bh * SEQ * HDIM;            // [key][dim]
    const __half* vbp = Vg + (size_t)bh * HDIM * SEQ;            // [dim][key]

    const int cc  = tid & 7;
    const int r16 = tid >> 3;

#define ATTN_COPY(kt, stage) do { \
    uint32_t _sK = sb + (stage) * AKV_STG; \
    uint32_t _sV = _sK + 8192; \
    _Pragma("unroll") \
    for (int i = 0; i < 4; i++) { \
        int R = r16 + 16 * i; \
        uint32_t _d = R * 128 + ((cc ^ (R & 7)) << 4); \
        cp_async16(_sK + _d, kbp + (size_t)((kt) + R) * HDIM + cc * 8); \
        cp_async16(_sV + _d, vbp + (size_t)R * SEQ + (kt) + cc * 8); \
    } \
} while (0)

    ATTN_COPY(0, 0);  CP_COMMIT();
    ATTN_COPY(64, 1); CP_COMMIT();

#pragma unroll 1
    for (int t = 0; t < 32; t++) {
        if (t < 31) CP_WAIT_1(); else CP_WAIT_0();
        __syncthreads();

        const uint32_t koff = (t & 1) * AKV_STG;
        const uint32_t voff = koff + 8192;

        // GEMM1: S = Q * K^T  (log2-domain logits)
        float sc[2][8][4];
#pragma unroll
        for (int mt = 0; mt < 2; mt++)
#pragma unroll
            for (int nt = 0; nt < 8; nt++)
#pragma unroll
                for (int rr = 0; rr < 4; rr++) sc[mt][nt][rr] = 0.f;

#pragma unroll
        for (int ks = 0; ks < 4; ks++) {
            const uint32_t kx = ((2 * ks) ^ s) << 4;
#pragma unroll
            for (int nt = 0; nt < 8; nt++) {
                uint32_t base = koff + (nt * 8 + s) * 128 + kx + q * 4;
                uint32_t b0 = lds32(smem, base);
                uint32_t b1 = lds32(smem, base ^ 16);
                mma_f16(sc[0][nt], qf[0][ks], b0, b1);
                mma_f16(sc[1][nt], qf[1][ks], b0, b1);
            }
        }

        // exp2-domain softmax; P packed in registers (c->a fragment identity)
        uint32_t pf[2][8][2];
#pragma unroll
        for (int mt = 0; mt < 2; mt++) {
            float rm0 = -1e30f, rm1 = -1e30f;
#pragma unroll
            for (int nt = 0; nt < 8; nt++) {
                rm0 = fmaxf(rm0, fmaxf(sc[mt][nt][0], sc[mt][nt][1]));
                rm1 = fmaxf(rm1, fmaxf(sc[mt][nt][2], sc[mt][nt][3]));
            }
            rm0 = fmaxf(rm0, __shfl_xor_sync(0xffffffffu, rm0, 1));
            rm0 = fmaxf(rm0, __shfl_xor_sync(0xffffffffu, rm0, 2));
            rm1 = fmaxf(rm1, __shfl_xor_sync(0xffffffffu, rm1, 1));
            rm1 = fmaxf(rm1, __shfl_xor_sync(0xffffffffu, rm1, 2));

            float mn0 = fmaxf(m[mt][0], rm0), mn1 = fmaxf(m[mt][1], rm1);
            float cr0 = fast_exp2(m[mt][0] - mn0), cr1 = fast_exp2(m[mt][1] - mn1);
            m[mt][0] = mn0; m[mt][1] = mn1;

#pragma unroll
            for (int nt = 0; nt < 8; nt++) {
                pf[mt][nt][0] = h2exp2_u32(pack_h2(sc[mt][nt][0] - mn0, sc[mt][nt][1] - mn0));
                pf[mt][nt][1] = h2exp2_u32(pack_h2(sc[mt][nt][2] - mn1, sc[mt][nt][3] - mn1));
            }

            // l sums via HADD2 tree (row s from [0], row s+8 from [1])
#pragma unroll
            for (int half = 0; half < 2; half++) {
                __half2 t01 = __hadd2(u2h2(pf[mt][0][half]), u2h2(pf[mt][1][half]));
                __half2 t23 = __hadd2(u2h2(pf[mt][2][half]), u2h2(pf[mt][3][half]));
                __half2 t45 = __hadd2(u2h2(pf[mt][4][half]), u2h2(pf[mt][5][half]));
                __half2 t67 = __hadd2(u2h2(pf[mt][6][half]), u2h2(pf[mt][7][half]));
                __half2 tt = __hadd2(__hadd2(t01, t23), __hadd2(t45, t67));
                float2 f = __half22float2(tt);
                float sum = f.x + f.y;
                sum += __shfl_xor_sync(0xffffffffu, sum, 1);
                sum += __shfl_xor_sync(0xffffffffu, sum, 2);
                float cr = half ? cr1 : cr0;
                l[mt][half] = l[mt][half] * cr + sum;
            }

#pragma unroll
            for (int nt = 0; nt < 8; nt++) {
                o[mt][nt][0] *= cr0; o[mt][nt][1] *= cr0;
                o[mt][nt][2] *= cr1; o[mt][nt][3] *= cr1;
            }
        }

        // GEMM2: O += P * V^T (A = pf registers, B = Vt smem)
#pragma unroll
        for (int kbi = 0; kbi < 4; kbi++) {
            uint32_t a0[4] = { pf[0][2*kbi][0], pf[0][2*kbi][1],
                               pf[0][2*kbi+1][0], pf[0][2*kbi+1][1] };
            uint32_t a1[4] = { pf[1][2*kbi][0], pf[1][2*kbi][1],
                               pf[1][2*kbi+1][0], pf[1][2*kbi+1][1] };
            const uint32_t kx = ((2 * kbi) ^ s) << 4;
#pragma unroll
            for (int nt = 0; nt < 8; nt++) {
                uint32_t base = voff + (nt * 8 + s) * 128 + kx + q * 4;
                uint32_t b0 = lds32(smem, base);
                uint32_t b1 = lds32(smem, base ^ 16);
                mma_f16(o[0][nt], a0, b0, b1);
                mma_f16(o[1][nt], a1, b0, b1);
            }
        }
        __syncthreads();
        if (t + 2 < 32) { ATTN_COPY((t + 2) * 64, t & 1); CP_COMMIT(); }
    }

    // finalize -> O half [B,N,DMODEL]
    int b = bh >> 4, h = bh & 15;
#pragma unroll
    for (int mt = 0; mt < 2; mt++) {
        float inv0 = 1.f / l[mt][0], inv1 = 1.f / l[mt][1];
        int n0 = qb * 128 + warp * 32 + mt * 16 + s;
        size_t base0 = ((size_t)(b * SEQ + n0)) * DMODEL + h * HDIM;
        size_t base1 = ((size_t)(b * SEQ + n0 + 8)) * DMODEL + h * HDIM;
#pragma unroll
        for (int nt = 0; nt < 8; nt++) {
            int c0 = nt * 8 + 2 * q;
            *(uint32_t*)&O[base0 + c0] = pack_h2(o[mt][nt][0] * inv0, o[mt][nt][1] * inv0);
            *(uint32_t*)&O[base1 + c0] = pack_h2(o[mt][nt][2] * inv1, o[mt][nt][3] * inv1);
        }
    }
}

// ---------------------------------------------------------------------------
extern "C" void kernel_launch(void* const* d_in, const int* in_sizes, int n_in,
                              void* d_out, int out_size)
{
    const float* x    = (const float*)d_in[0];
    const float* qpos = (const float*)d_in[1];
    const float* kpos = (const float*)d_in[2];
    const float* Wq = (const float*)d_in[3];
    const float* bq = (const float*)d_in[4];
    const float* Wk = (const float*)d_in[5];
    const float* bk = (const float*)d_in[6];
    const float* Wv = (const float*)d_in[7];
    const float* bv = (const float*)d_in[8];
    const float* Wo = (const float*)d_in[9];
    const float* bo = (const float*)d_in[10];
    float* out = (float*)d_out;

    __half *pq, *pk, *pv, *po, *pxh, *pwh;
    cudaGetSymbolAddress((void**)&pq, g_q);
    cudaGetSymbolAddress((void**)&pk, g_k);
    cudaGetSymbolAddress((void**)&pv, g_v);
    cudaGetSymbolAddress((void**)&po, g_o);
    cudaGetSymbolAddress((void**)&pxh, g_xh);
    cudaGetSymbolAddress((void**)&pwh, g_wh);

    cudaFuncSetAttribute(gemm_mma_kernel,
                         cudaFuncAttributeMaxDynamicSharedMemorySize, GEMM_SMEM);
    cudaFuncSetAttribute(attn_f16_kernel,
                         cudaFuncAttributeMaxDynamicSharedMemorySize, ATTN_SMEM);

    // one merged pre-convert launch
    CvtArgs ca;
    ca.src[0] = (const float4*)x;
    ca.src[1] = (const float4*)Wq;
    ca.src[2] = (const float4*)Wk;
    ca.src[3] = (const float4*)Wv;
    ca.src[4] = (const float4*)Wo;
    cvt_all_kernel<<<(NX4 + 4 * NW4) / 256, 256>>>(ca, (uint2*)pxh, (uint2*)pwh);

    // fused QKV projection (+rope on q,k; q pre-scaled by 0.125*log2e; V transposed)
    GemmArgs qkv;
    qkv.A = pxh;
    qkv.W[0] = pwh; qkv.W[1] = pwh + DMODEL * DMODEL; qkv.W[2] = pwh + 2 * DMODEL * DMODEL;
    qkv.bias[0] = bq; qkv.bias[1] = bk; qkv.bias[2] = bv;
    qkv.C[0] = pq; qkv.C[1] = pk; qkv.C[2] = pv;
    qkv.pos[0] = qpos; qkv.pos[1] = kpos; qkv.pos[2] = nullptr;
    qkv.layout_bhnd = 1;
    gemm_mma_kernel<<<dim3(24, 32), 256, GEMM_SMEM>>>(qkv);

    // attention
    attn_f16_kernel<<<BATCH * NHEADS * (SEQ / 128), 128, ATTN_SMEM>>>(pq, pk, pv, po);

    // output projection
    GemmArgs op;
    op.A = po;
    op.W[0] = op.W[1] = op.W[2] = pwh + 3 * DMODEL * DMODEL;
    op.bias[0] = op.bias[1] = op.bias[2] = bo;
    op.C[0] = op.C[1] = op.C[2] = out;
    op.pos[0] = op.pos[1] = op.pos[2] = nullptr;
    op.layout_bhnd = 0;
    gemm_mma_kernel<<<dim3(8, 32), 256, GEMM_SMEM>>>(op);
}

// round 10
// speedup vs baseline: 2.5804x; 1.0653x over previous
#include <cuda_runtime.h>
#include <cuda_fp16.h>
#include <math.h>
#include <stdint.h>

#define BATCH   2
#define SEQ     2048
#define DMODEL  1024
#define NHEADS  16
#define HDIM    64
#define M_ROWS  (BATCH*SEQ)
#define ROPE_SCALE 0.006135923151542565f      // 2*pi/1024
#define LOG2_1E4_OVER16 0.830482023721841f    // log2(10000)/16
#define QSCALE 0.1803368801111204f            // 0.125 * log2(e)

// Scratch (device globals: allocation-free)
__device__ __half g_q[BATCH*NHEADS*SEQ*HDIM];   // [B,H,N,D] fp16, *0.125*log2e, roped
__device__ __half g_k[BATCH*NHEADS*SEQ*HDIM];   // [B,H,N,D] fp16, roped
__device__ __half g_v[BATCH*NHEADS*HDIM*SEQ];   // [B,H,D,N] fp16 TRANSPOSED
__device__ __half g_o[BATCH*SEQ*DMODEL];        // [B,N,d] fp16
__device__ __half g_xh[M_ROWS*DMODEL];          // x as fp16
__device__ __half g_wh[4*DMODEL*DMODEL];        // Wq,Wk,Wv,Wo as fp16

// ---------------------------------------------------------------------------
// helpers
// ---------------------------------------------------------------------------
__device__ __forceinline__ float fast_exp2(float x) {
    float y;
    asm("ex2.approx.f32 %0, %1;" : "=f"(y) : "f"(x));
    return y;
}
__device__ __forceinline__ uint32_t smem_u32(const void* p) {
    uint32_t a;
    asm("{ .reg .u64 t; cvta.to.shared.u64 t, %1; cvt.u32.u64 %0, t; }"
        : "=r"(a) : "l"(p));
    return a;
}
__device__ __forceinline__ void cp_async16(uint32_t dst, const void* src) {
    asm volatile("cp.async.cg.shared.global [%0], [%1], 16;" :: "r"(dst), "l"(src));
}
#define CP_COMMIT()  asm volatile("cp.async.commit_group;" ::: "memory")
#define CP_WAIT_1()  asm volatile("cp.async.wait_group 1;" ::: "memory")
#define CP_WAIT_0()  asm volatile("cp.async.wait_group 0;" ::: "memory")

__device__ __forceinline__ uint32_t pack_h2(float a, float b) {
    __half2 h = __floats2half2_rn(a, b);
    return *(uint32_t*)&h;
}
__device__ __forceinline__ uint32_t h2exp2_u32(uint32_t x) {
    uint32_t y;
    asm("ex2.approx.f16x2 %0, %1;" : "=r"(y) : "r"(x));
    return y;
}
__device__ __forceinline__ __half2 u2h2(uint32_t x) { return *(__half2*)&x; }

// ldmatrix x4: 4 regs = one 16x16 A-fragment or two k16 B-fragments
__device__ __forceinline__ void ldsm_x4(uint32_t* r, uint32_t addr) {
    asm volatile("ldmatrix.sync.aligned.m8n8.x4.shared.b16 {%0,%1,%2,%3}, [%4];"
        : "=r"(r[0]), "=r"(r[1]), "=r"(r[2]), "=r"(r[3]) : "r"(addr));
}

// m16n8k16 fp16 MMA, fp32 accumulate
__device__ __forceinline__ void mma_f16(float c[4], const uint32_t a[4],
                                        uint32_t b0, uint32_t b1)
{
    asm volatile(
        "mma.sync.aligned.m16n8k16.row.col.f32.f16.f16.f32 "
        "{%0,%1,%2,%3}, {%4,%5,%6,%7}, {%8,%9}, {%0,%1,%2,%3};\n"
        : "+f"(c[0]), "+f"(c[1]), "+f"(c[2]), "+f"(c[3])
        : "r"(a[0]), "r"(a[1]), "r"(a[2]), "r"(a[3]), "r"(b0), "r"(b1));
}

// ---------------------------------------------------------------------------
// merged fp16 pre-convert
// ---------------------------------------------------------------------------
struct CvtArgs { const float4* src[5]; };
#define NX4 (M_ROWS*DMODEL/4)
#define NW4 (DMODEL*DMODEL/4)

__global__ void cvt_all_kernel(CvtArgs a, uint2* __restrict__ dstX,
                               uint2* __restrict__ dstW)
{
    int i = blockIdx.x * blockDim.x + threadIdx.x;
    float4 v;
    uint2* d;
    if (i < NX4) {
        v = a.src[0][i];
        d = dstX + i;
    } else {
        int j = i - NX4;
        v = a.src[1 + (j >> 18)][j & (NW4 - 1)];
        d = dstW + j;
    }
    *d = make_uint2(pack_h2(v.x, v.y), pack_h2(v.z, v.w));
}

// ---------------------------------------------------------------------------
// fp16 mma GEMM, cp.async + ldmatrix: C = A*W^T + bias (+rope)
// 256 threads, 8 warps (2M x 4N), CTA 128x128, BK=64 halves, 2 stages.
// ---------------------------------------------------------------------------
struct GemmArgs {
    const __half* A;
    const __half* W[3];
    const float*  bias[3];
    void*         C[3];
    const float*  pos[3];
    int layout_bhnd;
};

#define G_STG 32768
#define GEMM_SMEM (2*G_STG)

__global__ __launch_bounds__(256, 2)
void gemm_mma_kernel(GemmArgs args)
{
    extern __shared__ __align__(128) uint8_t smem[];
    const uint32_t sb = smem_u32(smem);

    const int tid  = threadIdx.x;
    const int warp = tid >> 5;
    const int lane = tid & 31;
    const int wm = (warp & 1) * 64;
    const int wn = (warp >> 1) * 32;
    const int proj = blockIdx.x >> 3;
    const int bn   = (blockIdx.x & 7) * 128;
    const int bm   = blockIdx.y * 128;

    const __half* A    = args.A;
    const __half* W    = args.W[proj];
    const float*  bias = args.bias[proj];
    const float*  pos  = args.pos[proj];

    // cp.async mapping
    const int cc = tid & 7;
    const int cr = tid >> 3;
    const __half* gA = A + (size_t)(bm + cr) * DMODEL + cc * 8;
    const __half* gB = W + (size_t)(bn + cr) * DMODEL + cc * 8;
    uint32_t cdst[4];
#pragma unroll
    for (int i = 0; i < 4; i++) {
        int R = cr + 32 * i;
        cdst[i] = R * 128 + ((cc ^ (R & 7)) << 4);
    }

#define GEMM_COPY(tile, stage) do { \
    uint32_t _sA = sb + (stage) * G_STG; \
    uint32_t _sB = _sA + 16384; \
    const __half* _ga = gA + (size_t)(tile) * 64; \
    const __half* _gb = gB + (size_t)(tile) * 64; \
    _Pragma("unroll") \
    for (int i = 0; i < 4; i++) { \
        cp_async16(_sA + cdst[i], _ga + (size_t)i * 32 * DMODEL); \
        cp_async16(_sB + cdst[i], _gb + (size_t)i * 32 * DMODEL); \
    } \
} while (0)

    float acc[4][4][4];
#pragma unroll
    for (int mt = 0; mt < 4; mt++)
#pragma unroll
        for (int nt = 0; nt < 4; nt++)
#pragma unroll
            for (int r = 0; r < 4; r++) acc[mt][nt][r] = 0.f;

    GEMM_COPY(0, 0); CP_COMMIT();
    GEMM_COPY(1, 1); CP_COMMIT();

    const int q = lane & 3;
    const int s = lane >> 2;

    // ldmatrix per-thread address components
    const int rlow = lane & 7;
    const int hbit = (lane >> 3) & 1;    // address group 2: rows+8 (A), chunk+1 (B)
    const int qbit = (lane >> 4) & 1;    // address groups 3/4: chunk+1 (A), rows+8 (B)
    uint32_t aSw[4], bSw[4];
#pragma unroll
    for (int kbi = 0; kbi < 4; kbi++) {
        aSw[kbi] = ((uint32_t)((2 * kbi + qbit) ^ rlow)) << 4;
        bSw[kbi] = ((uint32_t)((2 * kbi + hbit) ^ rlow)) << 4;
    }
    const uint32_t aRb = (uint32_t)(wm + hbit * 8 + rlow) * 128;
    const uint32_t bRb = (uint32_t)(wn + qbit * 8 + rlow) * 128 + 16384;

#pragma unroll 1
    for (int k0 = 0; k0 < 16; k0++) {
        if (k0 < 15) CP_WAIT_1(); else CP_WAIT_0();
        __syncthreads();

        const uint32_t soff = sb + (k0 & 1) * G_STG;

#pragma unroll
        for (int kbi = 0; kbi < 4; kbi++) {
            uint32_t af[4][4];
#pragma unroll
            for (int mt = 0; mt < 4; mt++)
                ldsm_x4(af[mt], soff + aRb + mt * 2048 + aSw[kbi]);
            uint32_t bf[2][4];
#pragma unroll
            for (int ntp = 0; ntp < 2; ntp++)
                ldsm_x4(bf[ntp], soff + bRb + ntp * 2048 + bSw[kbi]);
#pragma unroll
            for (int nt = 0; nt < 4; nt++) {
                uint32_t b0 = bf[nt >> 1][(nt & 1) * 2];
                uint32_t b1 = bf[nt >> 1][(nt & 1) * 2 + 1];
#pragma unroll
                for (int mt = 0; mt < 4; mt++)
                    mma_f16(acc[mt][nt], af[mt], b0, b1);
            }
        }
        __syncthreads();
        if (k0 + 2 < 16) { GEMM_COPY(k0 + 2, k0 & 1); CP_COMMIT(); }
    }

    // epilogue
    const float scl = (proj == 0 && args.layout_bhnd) ? QSCALE : 1.0f;
#pragma unroll
    for (int nt = 0; nt < 4; nt++) {
        int cg = bn + wn + nt * 8 + 2 * q;
        float bv0 = bias[cg], bv1 = bias[cg + 1];
        int dd = cg & 63;
        int hh = (cg >> 6) & (NHEADS - 1);
        int ip = (dd & 31) >> 1;
        int plane = (dd >> 5) & 1;
        float invf = fast_exp2(-LOG2_1E4_OVER16 * (float)ip) * ROPE_SCALE;
#pragma unroll
        for (int mt = 0; mt < 4; mt++) {
            int r0 = bm + wm + mt * 16 + s;
#pragma unroll
            for (int rr = 0; rr < 2; rr++) {
                int r = r0 + rr * 8;
                float v0 = acc[mt][nt][rr * 2 + 0] + bv0;
                float v1 = acc[mt][nt][rr * 2 + 1] + bv1;
                if (args.layout_bhnd) {
                    int b = r >> 11, n = r & 2047;
                    if (pos) {
                        float ang = pos[((size_t)(b * SEQ + n)) * 2 + plane] * invf;
                        float sn, cs;
                        __sincosf(ang, &sn, &cs);
                        float y0 = v0 * cs - v1 * sn;
                        float y1 = v0 * sn + v1 * cs;
                        v0 = y0; v1 = y1;
                    }
                    __half* Ch = (__half*)args.C[proj];
                    if (proj == 2) {
                        size_t tb = ((size_t)(b * NHEADS + hh) * HDIM + dd) * SEQ + n;
                        Ch[tb]       = __float2half_rn(v0);
                        Ch[tb + SEQ] = __float2half_rn(v1);
                    } else {
                        size_t base = (((size_t)(b * NHEADS + hh)) * SEQ + n) * HDIM + dd;
                        *(uint32_t*)&Ch[base] = pack_h2(v0 * scl, v1 * scl);
                    }
                } else {
                    float* Cf = (float*)args.C[proj];
                    *(float2*)&Cf[(size_t)r * DMODEL + cg] = make_float2(v0, v1);
                }
            }
        }
    }
}

// ---------------------------------------------------------------------------
// Flash attention, fp16 mma + ldmatrix, exp2-domain softmax, P in registers.
// 128 q-rows/CTA, 4 warps (warp tile 32x64). K [key64][dim64], V^T [dim64][key64].
// ---------------------------------------------------------------------------
#define AKV_STG 16384              // K 8KB + V 8KB per stage
#define ATTN_SMEM (2*AKV_STG)

__global__ __launch_bounds__(128)
void attn_f16_kernel(const __half* __restrict__ Q, const __half* __restrict__ Kg,
                     const __half* __restrict__ Vg, __half* __restrict__ O)
{
    extern __shared__ __align__(128) uint8_t smem[];
    const uint32_t sb = smem_u32(smem);

    const int tid  = threadIdx.x;
    const int warp = tid >> 5;
    const int lane = tid & 31;
    const int qb = blockIdx.x & 15;
    const int bh = blockIdx.x >> 4;

    const int q = lane & 3;
    const int s = lane >> 2;

    // Q fragments
    const uint32_t* qw = (const uint32_t*)(Q + ((size_t)bh * SEQ + qb * 128) * HDIM);
    uint32_t qf[2][4][4];
#pragma unroll
    for (int mt = 0; mt < 2; mt++) {
        int r = warp * 32 + mt * 16 + s;
#pragma unroll
        for (int ks = 0; ks < 4; ks++) {
            qf[mt][ks][0] = qw[(size_t)r * 32 + ks * 8 + q];
            qf[mt][ks][1] = qw[(size_t)(r + 8) * 32 + ks * 8 + q];
            qf[mt][ks][2] = qw[(size_t)r * 32 + ks * 8 + q + 4];
            qf[mt][ks][3] = qw[(size_t)(r + 8) * 32 + ks * 8 + q + 4];
        }
    }

    float m[2][2], l[2][2];
    float o[2][8][4];
#pragma unroll
    for (int mt = 0; mt < 2; mt++) {
        m[mt][0] = -1e30f; m[mt][1] = -1e30f;
        l[mt][0] = 0.f;    l[mt][1] = 0.f;
#pragma unroll
        for (int nt = 0; nt < 8; nt++)
#pragma unroll
            for (int rr = 0; rr < 4; rr++) o[mt][nt][rr] = 0.f;
    }

    const __half* kbp = Kg + (size_t)bh * SEQ * HDIM;            // [key][dim]
    const __half* vbp = Vg + (size_t)bh * HDIM * SEQ;            // [dim][key]

    const int cc  = tid & 7;
    const int r16 = tid >> 3;

#define ATTN_COPY(kt, stage) do { \
    uint32_t _sK = sb + (stage) * AKV_STG; \
    uint32_t _sV = _sK + 8192; \
    _Pragma("unroll") \
    for (int i = 0; i < 4; i++) { \
        int R = r16 + 16 * i; \
        uint32_t _d = R * 128 + ((cc ^ (R & 7)) << 4); \
        cp_async16(_sK + _d, kbp + (size_t)((kt) + R) * HDIM + cc * 8); \
        cp_async16(_sV + _d, vbp + (size_t)R * SEQ + (kt) + cc * 8); \
    } \
} while (0)

    ATTN_COPY(0, 0);  CP_COMMIT();
    ATTN_COPY(64, 1); CP_COMMIT();

    // ldmatrix B addressing (K and V tiles share geometry)
    const int rlow = lane & 7;
    const int hbit = (lane >> 3) & 1;   // chunk+1
    const int qbit = (lane >> 4) & 1;   // rows+8
    uint32_t kSw[4];
#pragma unroll
    for (int ks = 0; ks < 4; ks++)
        kSw[ks] = ((uint32_t)((2 * ks + hbit) ^ rlow)) << 4;
    const uint32_t nRb = (uint32_t)(qbit * 8 + rlow) * 128;

#pragma unroll 1
    for (int t = 0; t < 32; t++) {
        if (t < 31) CP_WAIT_1(); else CP_WAIT_0();
        __syncthreads();

        const uint32_t koff = sb + (t & 1) * AKV_STG;
        const uint32_t voff = koff + 8192;

        // GEMM1: S = Q * K^T  (log2-domain logits)
        float sc[2][8][4];
#pragma unroll
        for (int mt = 0; mt < 2; mt++)
#pragma unroll
            for (int nt = 0; nt < 8; nt++)
#pragma unroll
                for (int rr = 0; rr < 4; rr++) sc[mt][nt][rr] = 0.f;

#pragma unroll
        for (int ks = 0; ks < 4; ks++) {
#pragma unroll
            for (int ntp = 0; ntp < 4; ntp++) {
                uint32_t bf[4];
                ldsm_x4(bf, koff + nRb + ntp * 2048 + kSw[ks]);
                mma_f16(sc[0][2 * ntp],     qf[0][ks], bf[0], bf[1]);
                mma_f16(sc[1][2 * ntp],     qf[1][ks], bf[0], bf[1]);
                mma_f16(sc[0][2 * ntp + 1], qf[0][ks], bf[2], bf[3]);
                mma_f16(sc[1][2 * ntp + 1], qf[1][ks], bf[2], bf[3]);
            }
        }

        // exp2-domain softmax; P packed in registers
        uint32_t pf[2][8][2];
#pragma unroll
        for (int mt = 0; mt < 2; mt++) {
            float rm0 = -1e30f, rm1 = -1e30f;
#pragma unroll
            for (int nt = 0; nt < 8; nt++) {
                rm0 = fmaxf(rm0, fmaxf(sc[mt][nt][0], sc[mt][nt][1]));
                rm1 = fmaxf(rm1, fmaxf(sc[mt][nt][2], sc[mt][nt][3]));
            }
            rm0 = fmaxf(rm0, __shfl_xor_sync(0xffffffffu, rm0, 1));
            rm0 = fmaxf(rm0, __shfl_xor_sync(0xffffffffu, rm0, 2));
            rm1 = fmaxf(rm1, __shfl_xor_sync(0xffffffffu, rm1, 1));
            rm1 = fmaxf(rm1, __shfl_xor_sync(0xffffffffu, rm1, 2));

            float mn0 = fmaxf(m[mt][0], rm0), mn1 = fmaxf(m[mt][1], rm1);
            float cr0 = fast_exp2(m[mt][0] - mn0), cr1 = fast_exp2(m[mt][1] - mn1);
            m[mt][0] = mn0; m[mt][1] = mn1;

#pragma unroll
            for (int nt = 0; nt < 8; nt++) {
                pf[mt][nt][0] = h2exp2_u32(pack_h2(sc[mt][nt][0] - mn0, sc[mt][nt][1] - mn0));
                pf[mt][nt][1] = h2exp2_u32(pack_h2(sc[mt][nt][2] - mn1, sc[mt][nt][3] - mn1));
            }

            // l sums via HADD2 tree
#pragma unroll
            for (int half = 0; half < 2; half++) {
                __half2 t01 = __hadd2(u2h2(pf[mt][0][half]), u2h2(pf[mt][1][half]));
                __half2 t23 = __hadd2(u2h2(pf[mt][2][half]), u2h2(pf[mt][3][half]));
                __half2 t45 = __hadd2(u2h2(pf[mt][4][half]), u2h2(pf[mt][5][half]));
                __half2 t67 = __hadd2(u2h2(pf[mt][6][half]), u2h2(pf[mt][7][half]));
                __half2 tt = __hadd2(__hadd2(t01, t23), __hadd2(t45, t67));
                float2 f = __half22float2(tt);
                float sum = f.x + f.y;
                sum += __shfl_xor_sync(0xffffffffu, sum, 1);
                sum += __shfl_xor_sync(0xffffffffu, sum, 2);
                float cr = half ? cr1 : cr0;
                l[mt][half] = l[mt][half] * cr + sum;
            }

            // skip exact-noop rescale (all corrections == 1 across the warp)
            if (!__all_sync(0xffffffffu, (cr0 == 1.f) && (cr1 == 1.f))) {
#pragma unroll
                for (int nt = 0; nt < 8; nt++) {
                    o[mt][nt][0] *= cr0; o[mt][nt][1] *= cr0;
                    o[mt][nt][2] *= cr1; o[mt][nt][3] *= cr1;
                }
            }
        }

        // GEMM2: O += P * V^T (A = pf registers, B = Vt via ldmatrix)
#pragma unroll
        for (int kbi = 0; kbi < 4; kbi++) {
            uint32_t a0[4] = { pf[0][2*kbi][0], pf[0][2*kbi][1],
                               pf[0][2*kbi+1][0], pf[0][2*kbi+1][1] };
            uint32_t a1[4] = { pf[1][2*kbi][0], pf[1][2*kbi][1],
                               pf[1][2*kbi+1][0], pf[1][2*kbi+1][1] };
#pragma unroll
            for (int ntp = 0; ntp < 4; ntp++) {
                uint32_t bf[4];
                ldsm_x4(bf, voff + nRb + ntp * 2048 + kSw[kbi]);
                mma_f16(o[0][2 * ntp],     a0, bf[0], bf[1]);
                mma_f16(o[1][2 * ntp],     a1, bf[0], bf[1]);
                mma_f16(o[0][2 * ntp + 1], a0, bf[2], bf[3]);
                mma_f16(o[1][2 * ntp + 1], a1, bf[2], bf[3]);
            }
        }
        __syncthreads();
        if (t + 2 < 32) { ATTN_COPY((t + 2) * 64, t & 1); CP_COMMIT(); }
    }

    // finalize -> O half [B,N,DMODEL]
    int b = bh >> 4, h = bh & 15;
#pragma unroll
    for (int mt = 0; mt < 2; mt++) {
        float inv0 = 1.f / l[mt][0], inv1 = 1.f / l[mt][1];
        int n0 = qb * 128 + warp * 32 + mt * 16 + s;
        size_t base0 = ((size_t)(b * SEQ + n0)) * DMODEL + h * HDIM;
        size_t base1 = ((size_t)(b * SEQ + n0 + 8)) * DMODEL + h * HDIM;
#pragma unroll
        for (int nt = 0; nt < 8; nt++) {
            int c0 = nt * 8 + 2 * q;
            *(uint32_t*)&O[base0 + c0] = pack_h2(o[mt][nt][0] * inv0, o[mt][nt][1] * inv0);
            *(uint32_t*)&O[base1 + c0] = pack_h2(o[mt][nt][2] * inv1, o[mt][nt][3] * inv1);
        }
    }
}

// ---------------------------------------------------------------------------
extern "C" void kernel_launch(void* const* d_in, const int* in_sizes, int n_in,
                              void* d_out, int out_size)
{
    const float* x    = (const float*)d_in[0];
    const float* qpos = (const float*)d_in[1];
    const float* kpos = (const float*)d_in[2];
    const float* Wq = (const float*)d_in[3];
    const float* bq = (const float*)d_in[4];
    const float* Wk = (const float*)d_in[5];
    const float* bk = (const float*)d_in[6];
    const float* Wv = (const float*)d_in[7];
    const float* bv = (const float*)d_in[8];
    const float* Wo = (const float*)d_in[9];
    const float* bo = (const float*)d_in[10];
    float* out = (float*)d_out;

    __half *pq, *pk, *pv, *po, *pxh, *pwh;
    cudaGetSymbolAddress((void**)&pq, g_q);
    cudaGetSymbolAddress((void**)&pk, g_k);
    cudaGetSymbolAddress((void**)&pv, g_v);
    cudaGetSymbolAddress((void**)&po, g_o);
    cudaGetSymbolAddress((void**)&pxh, g_xh);
    cudaGetSymbolAddress((void**)&pwh, g_wh);

    cudaFuncSetAttribute(gemm_mma_kernel,
                         cudaFuncAttributeMaxDynamicSharedMemorySize, GEMM_SMEM);
    cudaFuncSetAttribute(attn_f16_kernel,
                         cudaFuncAttributeMaxDynamicSharedMemorySize, ATTN_SMEM);

    // one merged pre-convert launch
    CvtArgs ca;
    ca.src[0] = (const float4*)x;
    ca.src[1] = (const float4*)Wq;
    ca.src[2] = (const float4*)Wk;
    ca.src[3] = (const float4*)Wv;
    ca.src[4] = (const float4*)Wo;
    cvt_all_kernel<<<(NX4 + 4 * NW4) / 256, 256>>>(ca, (uint2*)pxh, (uint2*)pwh);

    // fused QKV projection (+rope; q pre-scaled by 0.125*log2e; V transposed)
    GemmArgs qkv;
    qkv.A = pxh;
    qkv.W[0] = pwh; qkv.W[1] = pwh + DMODEL * DMODEL; qkv.W[2] = pwh + 2 * DMODEL * DMODEL;
    qkv.bias[0] = bq; qkv.bias[1] = bk; qkv.bias[2] = bv;
    qkv.C[0] = pq; qkv.C[1] = pk; qkv.C[2] = pv;
    qkv.pos[0] = qpos; qkv.pos[1] = kpos; qkv.pos[2] = nullptr;
    qkv.layout_bhnd = 1;
    gemm_mma_kernel<<<dim3(24, 32), 256, GEMM_SMEM>>>(qkv);

    // attention
    attn_f16_kernel<<<BATCH * NHEADS * (SEQ / 128), 128, ATTN_SMEM>>>(pq, pk, pv, po);

    // output projection
    GemmArgs op;
    op.A = po;
    op.W[0] = op.W[1] = op.W[2] = pwh + 3 * DMODEL * DMODEL;
    op.bias[0] = op.bias[1] = op.bias[2] = bo;
    op.C[0] = op.C[1] = op.C[2] = out;
    op.pos[0] = op.pos[1] = op.pos[2] = nullptr;
    op.layout_bhnd = 0;
    gemm_mma_kernel<<<dim3(8, 32), 256, GEMM_SMEM>>>(op);
}

// round 11
// speedup vs baseline: 2.5962x; 1.0061x over previous
#include <cuda_runtime.h>
#include <cuda_fp16.h>
#include <math.h>
#include <stdint.h>

#define BATCH   2
#define SEQ     2048
#define DMODEL  1024
#define NHEADS  16
#define HDIM    64
#define M_ROWS  (BATCH*SEQ)
#define ROPE_SCALE 0.006135923151542565f      // 2*pi/1024
#define LOG2_1E4_OVER16 0.830482023721841f    // log2(10000)/16
#define QSCALE 0.1803368801111204f            // 0.125 * log2(e)

// Scratch (device globals: allocation-free)
__device__ __half g_q[BATCH*NHEADS*SEQ*HDIM];   // [B,H,N,D] fp16, *0.125*log2e, roped
__device__ __half g_k[BATCH*NHEADS*SEQ*HDIM];   // [B,H,N,D] fp16, roped
__device__ __half g_v[BATCH*NHEADS*HDIM*SEQ];   // [B,H,D,N] fp16 TRANSPOSED
__device__ __half g_o[BATCH*SEQ*DMODEL];        // [B,N,d] fp16
__device__ __half g_xh[M_ROWS*DMODEL];          // x as fp16
__device__ __half g_wh[4*DMODEL*DMODEL];        // Wq,Wk,Wv,Wo as fp16

// ---------------------------------------------------------------------------
// helpers
// ---------------------------------------------------------------------------
__device__ __forceinline__ float fast_exp2(float x) {
    float y;
    asm("ex2.approx.f32 %0, %1;" : "=f"(y) : "f"(x));
    return y;
}
__device__ __forceinline__ uint32_t smem_u32(const void* p) {
    uint32_t a;
    asm("{ .reg .u64 t; cvta.to.shared.u64 t, %1; cvt.u32.u64 %0, t; }"
        : "=r"(a) : "l"(p));
    return a;
}
__device__ __forceinline__ void cp_async16(uint32_t dst, const void* src) {
    asm volatile("cp.async.cg.shared.global [%0], [%1], 16;" :: "r"(dst), "l"(src));
}
#define CP_COMMIT()  asm volatile("cp.async.commit_group;" ::: "memory")
#define CP_WAIT_1()  asm volatile("cp.async.wait_group 1;" ::: "memory")
#define CP_WAIT_0()  asm volatile("cp.async.wait_group 0;" ::: "memory")

__device__ __forceinline__ uint32_t pack_h2(float a, float b) {
    __half2 h = __floats2half2_rn(a, b);
    return *(uint32_t*)&h;
}
__device__ __forceinline__ uint32_t h2exp2_u32(uint32_t x) {
    uint32_t y;
    asm("ex2.approx.f16x2 %0, %1;" : "=r"(y) : "r"(x));
    return y;
}
__device__ __forceinline__ __half2 u2h2(uint32_t x) { return *(__half2*)&x; }

__device__ __forceinline__ void ldsm_x4(uint32_t* r, uint32_t addr) {
    asm volatile("ldmatrix.sync.aligned.m8n8.x4.shared.b16 {%0,%1,%2,%3}, [%4];"
        : "=r"(r[0]), "=r"(r[1]), "=r"(r[2]), "=r"(r[3]) : "r"(addr));
}

// m16n8k16 fp16 MMA, fp32 accumulate
__device__ __forceinline__ void mma_f16(float c[4], const uint32_t a[4],
                                        uint32_t b0, uint32_t b1)
{
    asm volatile(
        "mma.sync.aligned.m16n8k16.row.col.f32.f16.f16.f32 "
        "{%0,%1,%2,%3}, {%4,%5,%6,%7}, {%8,%9}, {%0,%1,%2,%3};\n"
        : "+f"(c[0]), "+f"(c[1]), "+f"(c[2]), "+f"(c[3])
        : "r"(a[0]), "r"(a[1]), "r"(a[2]), "r"(a[3]), "r"(b0), "r"(b1));
}

// ---------------------------------------------------------------------------
// merged fp16 pre-convert
// ---------------------------------------------------------------------------
struct CvtArgs { const float4* src[5]; };
#define NX4 (M_ROWS*DMODEL/4)
#define NW4 (DMODEL*DMODEL/4)

__global__ void cvt_all_kernel(CvtArgs a, uint2* __restrict__ dstX,
                               uint2* __restrict__ dstW)
{
    int i = blockIdx.x * blockDim.x + threadIdx.x;
    float4 v;
    uint2* d;
    if (i < NX4) {
        v = a.src[0][i];
        d = dstX + i;
    } else {
        int j = i - NX4;
        v = a.src[1 + (j >> 18)][j & (NW4 - 1)];
        d = dstW + j;
    }
    *d = make_uint2(pack_h2(v.x, v.y), pack_h2(v.z, v.w));
}

// ---------------------------------------------------------------------------
// fp16 mma GEMM, cp.async + ldmatrix, 3-stage pipeline (ONE sync/iter).
// 256 threads, 8 warps (2M x 4N), CTA 128x128, BK=64 halves.
// ---------------------------------------------------------------------------
struct GemmArgs {
    const __half* A;
    const __half* W[3];
    const float*  bias[3];
    void*         C[3];
    const float*  pos[3];
    int layout_bhnd;
};

#define G_STG 32768
#define GEMM_SMEM (3*G_STG)

__global__ __launch_bounds__(256, 2)
void gemm_mma_kernel(GemmArgs args)
{
    extern __shared__ __align__(128) uint8_t smem[];
    const uint32_t sb = smem_u32(smem);

    const int tid  = threadIdx.x;
    const int warp = tid >> 5;
    const int lane = tid & 31;
    const int wm = (warp & 1) * 64;
    const int wn = (warp >> 1) * 32;
    const int proj = blockIdx.x >> 3;
    const int bn   = (blockIdx.x & 7) * 128;
    const int bm   = blockIdx.y * 128;

    const __half* A    = args.A;
    const __half* W    = args.W[proj];
    const float*  bias = args.bias[proj];
    const float*  pos  = args.pos[proj];

    // cp.async mapping
    const int cc = tid & 7;
    const int cr = tid >> 3;
    const __half* gA = A + (size_t)(bm + cr) * DMODEL + cc * 8;
    const __half* gB = W + (size_t)(bn + cr) * DMODEL + cc * 8;
    uint32_t cdst[4];
#pragma unroll
    for (int i = 0; i < 4; i++) {
        int R = cr + 32 * i;
        cdst[i] = R * 128 + ((cc ^ (R & 7)) << 4);
    }

#define GEMM_COPY(tile, stage) do { \
    uint32_t _sA = sb + (stage) * G_STG; \
    uint32_t _sB = _sA + 16384; \
    const __half* _ga = gA + (size_t)(tile) * 64; \
    const __half* _gb = gB + (size_t)(tile) * 64; \
    _Pragma("unroll") \
    for (int i = 0; i < 4; i++) { \
        cp_async16(_sA + cdst[i], _ga + (size_t)i * 32 * DMODEL); \
        cp_async16(_sB + cdst[i], _gb + (size_t)i * 32 * DMODEL); \
    } \
} while (0)

    float acc[4][4][4];
#pragma unroll
    for (int mt = 0; mt < 4; mt++)
#pragma unroll
        for (int nt = 0; nt < 4; nt++)
#pragma unroll
            for (int r = 0; r < 4; r++) acc[mt][nt][r] = 0.f;

    GEMM_COPY(0, 0); CP_COMMIT();
    GEMM_COPY(1, 1); CP_COMMIT();

    const int q = lane & 3;
    const int s = lane >> 2;

    // ldmatrix per-thread address components
    const int rlow = lane & 7;
    const int hbit = (lane >> 3) & 1;
    const int qbit = (lane >> 4) & 1;
    uint32_t aSw[4], bSw[4];
#pragma unroll
    for (int kbi = 0; kbi < 4; kbi++) {
        aSw[kbi] = ((uint32_t)((2 * kbi + qbit) ^ rlow)) << 4;
        bSw[kbi] = ((uint32_t)((2 * kbi + hbit) ^ rlow)) << 4;
    }
    const uint32_t aRb = (uint32_t)(wm + hbit * 8 + rlow) * 128;
    const uint32_t bRb = (uint32_t)(wn + qbit * 8 + rlow) * 128 + 16384;

    int ms = 0, ps = 2;   // compute stage, prefetch stage (mod 3)
#pragma unroll 1
    for (int k0 = 0; k0 < 16; k0++) {
        if (k0 < 15) CP_WAIT_1(); else CP_WAIT_0();
        __syncthreads();
        // prefetch tile k0+2 into stage ps (buffer consumed in iter k0-1; safe)
        if (k0 + 2 < 16) { GEMM_COPY(k0 + 2, ps); CP_COMMIT(); }

        const uint32_t soff = sb + ms * G_STG;

#pragma unroll
        for (int kbi = 0; kbi < 4; kbi++) {
            uint32_t af[4][4];
#pragma unroll
            for (int mt = 0; mt < 4; mt++)
                ldsm_x4(af[mt], soff + aRb + mt * 2048 + aSw[kbi]);
            uint32_t bf[2][4];
#pragma unroll
            for (int ntp = 0; ntp < 2; ntp++)
                ldsm_x4(bf[ntp], soff + bRb + ntp * 2048 + bSw[kbi]);
#pragma unroll
            for (int nt = 0; nt < 4; nt++) {
                uint32_t b0 = bf[nt >> 1][(nt & 1) * 2];
                uint32_t b1 = bf[nt >> 1][(nt & 1) * 2 + 1];
#pragma unroll
                for (int mt = 0; mt < 4; mt++)
                    mma_f16(acc[mt][nt], af[mt], b0, b1);
            }
        }
        ms = (ms == 2) ? 0 : ms + 1;
        ps = (ps == 2) ? 0 : ps + 1;
    }

    // epilogue
    const float scl = (proj == 0 && args.layout_bhnd) ? QSCALE : 1.0f;
#pragma unroll
    for (int nt = 0; nt < 4; nt++) {
        int cg = bn + wn + nt * 8 + 2 * q;
        float bv0 = bias[cg], bv1 = bias[cg + 1];
        int dd = cg & 63;
        int hh = (cg >> 6) & (NHEADS - 1);
        int ip = (dd & 31) >> 1;
        int plane = (dd >> 5) & 1;
        float invf = fast_exp2(-LOG2_1E4_OVER16 * (float)ip) * ROPE_SCALE;
#pragma unroll
        for (int mt = 0; mt < 4; mt++) {
            int r0 = bm + wm + mt * 16 + s;
#pragma unroll
            for (int rr = 0; rr < 2; rr++) {
                int r = r0 + rr * 8;
                float v0 = acc[mt][nt][rr * 2 + 0] + bv0;
                float v1 = acc[mt][nt][rr * 2 + 1] + bv1;
                if (args.layout_bhnd) {
                    int b = r >> 11, n = r & 2047;
                    if (pos) {
                        float ang = pos[((size_t)(b * SEQ + n)) * 2 + plane] * invf;
                        float sn, cs;
                        __sincosf(ang, &sn, &cs);
                        float y0 = v0 * cs - v1 * sn;
                        float y1 = v0 * sn + v1 * cs;
                        v0 = y0; v1 = y1;
                    }
                    __half* Ch = (__half*)args.C[proj];
                    if (proj == 2) {
                        size_t tb = ((size_t)(b * NHEADS + hh) * HDIM + dd) * SEQ + n;
                        Ch[tb]       = __float2half_rn(v0);
                        Ch[tb + SEQ] = __float2half_rn(v1);
                    } else {
                        size_t base = (((size_t)(b * NHEADS + hh)) * SEQ + n) * HDIM + dd;
                        *(uint32_t*)&Ch[base] = pack_h2(v0 * scl, v1 * scl);
                    }
                } else {
                    float* Cf = (float*)args.C[proj];
                    *(float2*)&Cf[(size_t)r * DMODEL + cg] = make_float2(v0, v1);
                }
            }
        }
    }
}

// ---------------------------------------------------------------------------
// Flash attention, fp16 mma + ldmatrix, 3-stage pipeline (ONE sync/iter).
// 128 q-rows/CTA, 4 warps (warp tile 32x64). K [key64][dim64], V^T [dim64][key64].
// ---------------------------------------------------------------------------
#define AKV_STG 16384              // K 8KB + V 8KB per stage
#define ATTN_SMEM (3*AKV_STG)

__global__ __launch_bounds__(128)
void attn_f16_kernel(const __half* __restrict__ Q, const __half* __restrict__ Kg,
                     const __half* __restrict__ Vg, __half* __restrict__ O)
{
    extern __shared__ __align__(128) uint8_t smem[];
    const uint32_t sb = smem_u32(smem);

    const int tid  = threadIdx.x;
    const int warp = tid >> 5;
    const int lane = tid & 31;
    const int qb = blockIdx.x & 15;
    const int bh = blockIdx.x >> 4;

    const int q = lane & 3;
    const int s = lane >> 2;

    // Q fragments
    const uint32_t* qw = (const uint32_t*)(Q + ((size_t)bh * SEQ + qb * 128) * HDIM);
    uint32_t qf[2][4][4];
#pragma unroll
    for (int mt = 0; mt < 2; mt++) {
        int r = warp * 32 + mt * 16 + s;
#pragma unroll
        for (int ks = 0; ks < 4; ks++) {
            qf[mt][ks][0] = qw[(size_t)r * 32 + ks * 8 + q];
            qf[mt][ks][1] = qw[(size_t)(r + 8) * 32 + ks * 8 + q];
            qf[mt][ks][2] = qw[(size_t)r * 32 + ks * 8 + q + 4];
            qf[mt][ks][3] = qw[(size_t)(r + 8) * 32 + ks * 8 + q + 4];
        }
    }

    float m[2][2], l[2][2];
    float o[2][8][4];
#pragma unroll
    for (int mt = 0; mt < 2; mt++) {
        m[mt][0] = -1e30f; m[mt][1] = -1e30f;
        l[mt][0] = 0.f;    l[mt][1] = 0.f;
#pragma unroll
        for (int nt = 0; nt < 8; nt++)
#pragma unroll
            for (int rr = 0; rr < 4; rr++) o[mt][nt][rr] = 0.f;
    }

    const __half* kbp = Kg + (size_t)bh * SEQ * HDIM;            // [key][dim]
    const __half* vbp = Vg + (size_t)bh * HDIM * SEQ;            // [dim][key]

    const int cc  = tid & 7;
    const int r16 = tid >> 3;

#define ATTN_COPY(kt, stage) do { \
    uint32_t _sK = sb + (stage) * AKV_STG; \
    uint32_t _sV = _sK + 8192; \
    _Pragma("unroll") \
    for (int i = 0; i < 4; i++) { \
        int R = r16 + 16 * i; \
        uint32_t _d = R * 128 + ((cc ^ (R & 7)) << 4); \
        cp_async16(_sK + _d, kbp + (size_t)((kt) + R) * HDIM + cc * 8); \
        cp_async16(_sV + _d, vbp + (size_t)R * SEQ + (kt) + cc * 8); \
    } \
} while (0)

    ATTN_COPY(0, 0);  CP_COMMIT();
    ATTN_COPY(64, 1); CP_COMMIT();

    // ldmatrix B addressing
    const int rlow = lane & 7;
    const int hbit = (lane >> 3) & 1;
    const int qbit = (lane >> 4) & 1;
    uint32_t kSw[4];
#pragma unroll
    for (int ks = 0; ks < 4; ks++)
        kSw[ks] = ((uint32_t)((2 * ks + hbit) ^ rlow)) << 4;
    const uint32_t nRb = (uint32_t)(qbit * 8 + rlow) * 128;

    int ms = 0, ps = 2;
#pragma unroll 1
    for (int t = 0; t < 32; t++) {
        if (t < 31) CP_WAIT_1(); else CP_WAIT_0();
        __syncthreads();
        if (t + 2 < 32) { ATTN_COPY((t + 2) * 64, ps); CP_COMMIT(); }

        const uint32_t koff = sb + ms * AKV_STG;
        const uint32_t voff = koff + 8192;

        // GEMM1: S = Q * K^T  (log2-domain logits)
        float sc[2][8][4];
#pragma unroll
        for (int mt = 0; mt < 2; mt++)
#pragma unroll
            for (int nt = 0; nt < 8; nt++)
#pragma unroll
                for (int rr = 0; rr < 4; rr++) sc[mt][nt][rr] = 0.f;

#pragma unroll
        for (int ks = 0; ks < 4; ks++) {
#pragma unroll
            for (int ntp = 0; ntp < 4; ntp++) {
                uint32_t bf[4];
                ldsm_x4(bf, koff + nRb + ntp * 2048 + kSw[ks]);
                mma_f16(sc[0][2 * ntp],     qf[0][ks], bf[0], bf[1]);
                mma_f16(sc[1][2 * ntp],     qf[1][ks], bf[0], bf[1]);
                mma_f16(sc[0][2 * ntp + 1], qf[0][ks], bf[2], bf[3]);
                mma_f16(sc[1][2 * ntp + 1], qf[1][ks], bf[2], bf[3]);
            }
        }

        // exp2-domain softmax; P packed in registers
        uint32_t pf[2][8][2];
#pragma unroll
        for (int mt = 0; mt < 2; mt++) {
            float rm0 = -1e30f, rm1 = -1e30f;
#pragma unroll
            for (int nt = 0; nt < 8; nt++) {
                rm0 = fmaxf(rm0, fmaxf(sc[mt][nt][0], sc[mt][nt][1]));
                rm1 = fmaxf(rm1, fmaxf(sc[mt][nt][2], sc[mt][nt][3]));
            }
            rm0 = fmaxf(rm0, __shfl_xor_sync(0xffffffffu, rm0, 1));
            rm0 = fmaxf(rm0, __shfl_xor_sync(0xffffffffu, rm0, 2));
            rm1 = fmaxf(rm1, __shfl_xor_sync(0xffffffffu, rm1, 1));
            rm1 = fmaxf(rm1, __shfl_xor_sync(0xffffffffu, rm1, 2));

            float mn0 = fmaxf(m[mt][0], rm0), mn1 = fmaxf(m[mt][1], rm1);
            float cr0 = fast_exp2(m[mt][0] - mn0), cr1 = fast_exp2(m[mt][1] - mn1);
            m[mt][0] = mn0; m[mt][1] = mn1;

#pragma unroll
            for (int nt = 0; nt < 8; nt++) {
                pf[mt][nt][0] = h2exp2_u32(pack_h2(sc[mt][nt][0] - mn0, sc[mt][nt][1] - mn0));
                pf[mt][nt][1] = h2exp2_u32(pack_h2(sc[mt][nt][2] - mn1, sc[mt][nt][3] - mn1));
            }

            // l sums via HADD2 tree
#pragma unroll
            for (int half = 0; half < 2; half++) {
                __half2 t01 = __hadd2(u2h2(pf[mt][0][half]), u2h2(pf[mt][1][half]));
                __half2 t23 = __hadd2(u2h2(pf[mt][2][half]), u2h2(pf[mt][3][half]));
                __half2 t45 = __hadd2(u2h2(pf[mt][4][half]), u2h2(pf[mt][5][half]));
                __half2 t67 = __hadd2(u2h2(pf[mt][6][half]), u2h2(pf[mt][7][half]));
                __half2 tt = __hadd2(__hadd2(t01, t23), __hadd2(t45, t67));
                float2 f = __half22float2(tt);
                float sum = f.x + f.y;
                sum += __shfl_xor_sync(0xffffffffu, sum, 1);
                sum += __shfl_xor_sync(0xffffffffu, sum, 2);
                float cr = half ? cr1 : cr0;
                l[mt][half] = l[mt][half] * cr + sum;
            }

            // skip exact-noop rescale
            if (!__all_sync(0xffffffffu, (cr0 == 1.f) && (cr1 == 1.f))) {
#pragma unroll
                for (int nt = 0; nt < 8; nt++) {
                    o[mt][nt][0] *= cr0; o[mt][nt][1] *= cr0;
                    o[mt][nt][2] *= cr1; o[mt][nt][3] *= cr1;
                }
            }
        }

        // GEMM2: O += P * V^T
#pragma unroll
        for (int kbi = 0; kbi < 4; kbi++) {
            uint32_t a0[4] = { pf[0][2*kbi][0], pf[0][2*kbi][1],
                               pf[0][2*kbi+1][0], pf[0][2*kbi+1][1] };
            uint32_t a1[4] = { pf[1][2*kbi][0], pf[1][2*kbi][1],
                               pf[1][2*kbi+1][0], pf[1][2*kbi+1][1] };
#pragma unroll
            for (int ntp = 0; ntp < 4; ntp++) {
                uint32_t bf[4];
                ldsm_x4(bf, voff + nRb + ntp * 2048 + kSw[kbi]);
                mma_f16(o[0][2 * ntp],     a0, bf[0], bf[1]);
                mma_f16(o[1][2 * ntp],     a1, bf[0], bf[1]);
                mma_f16(o[0][2 * ntp + 1], a0, bf[2], bf[3]);
                mma_f16(o[1][2 * ntp + 1], a1, bf[2], bf[3]);
            }
        }
        ms = (ms == 2) ? 0 : ms + 1;
        ps = (ps == 2) ? 0 : ps + 1;
    }

    // finalize -> O half [B,N,DMODEL]
    int b = bh >> 4, h = bh & 15;
#pragma unroll
    for (int mt = 0; mt < 2; mt++) {
        float inv0 = 1.f / l[mt][0], inv1 = 1.f / l[mt][1];
        int n0 = qb * 128 + warp * 32 + mt * 16 + s;
        size_t base0 = ((size_t)(b * SEQ + n0)) * DMODEL + h * HDIM;
        size_t base1 = ((size_t)(b * SEQ + n0 + 8)) * DMODEL + h * HDIM;
#pragma unroll
        for (int nt = 0; nt < 8; nt++) {
            int c0 = nt * 8 + 2 * q;
            *(uint32_t*)&O[base0 + c0] = pack_h2(o[mt][nt][0] * inv0, o[mt][nt][1] * inv0);
            *(uint32_t*)&O[base1 + c0] = pack_h2(o[mt][nt][2] * inv1, o[mt][nt][3] * inv1);
        }
    }
}

// ---------------------------------------------------------------------------
extern "C" void kernel_launch(void* const* d_in, const int* in_sizes, int n_in,
                              void* d_out, int out_size)
{
    const float* x    = (const float*)d_in[0];
    const float* qpos = (const float*)d_in[1];
    const float* kpos = (const float*)d_in[2];
    const float* Wq = (const float*)d_in[3];
    const float* bq = (const float*)d_in[4];
    const float* Wk = (const float*)d_in[5];
    const float* bk = (const float*)d_in[6];
    const float* Wv = (const float*)d_in[7];
    const float* bv = (const float*)d_in[8];
    const float* Wo = (const float*)d_in[9];
    const float* bo = (const float*)d_in[10];
    float* out = (float*)d_out;

    __half *pq, *pk, *pv, *po, *pxh, *pwh;
    cudaGetSymbolAddress((void**)&pq, g_q);
    cudaGetSymbolAddress((void**)&pk, g_k);
    cudaGetSymbolAddress((void**)&pv, g_v);
    cudaGetSymbolAddress((void**)&po, g_o);
    cudaGetSymbolAddress((void**)&pxh, g_xh);
    cudaGetSymbolAddress((void**)&pwh, g_wh);

    cudaFuncSetAttribute(gemm_mma_kernel,
                         cudaFuncAttributeMaxDynamicSharedMemorySize, GEMM_SMEM);
    cudaFuncSetAttribute(attn_f16_kernel,
                         cudaFuncAttributeMaxDynamicSharedMemorySize, ATTN_SMEM);

    // one merged pre-convert launch
    CvtArgs ca;
    ca.src[0] = (const float4*)x;
    ca.src[1] = (const float4*)Wq;
    ca.src[2] = (const float4*)Wk;
    ca.src[3] = (const float4*)Wv;
    ca.src[4] = (const float4*)Wo;
    cvt_all_kernel<<<(NX4 + 4 * NW4) / 256, 256>>>(ca, (uint2*)pxh, (uint2*)pwh);

    // fused QKV projection (+rope; q pre-scaled by 0.125*log2e; V transposed)
    GemmArgs qkv;
    qkv.A = pxh;
    qkv.W[0] = pwh; qkv.W[1] = pwh + DMODEL * DMODEL; qkv.W[2] = pwh + 2 * DMODEL * DMODEL;
    qkv.bias[0] = bq; qkv.bias[1] = bk; qkv.bias[2] = bv;
    qkv.C[0] = pq; qkv.C[1] = pk; qkv.C[2] = pv;
    qkv.pos[0] = qpos; qkv.pos[1] = kpos; qkv.pos[2] = nullptr;
    qkv.layout_bhnd = 1;
    gemm_mma_kernel<<<dim3(24, 32), 256, GEMM_SMEM>>>(qkv);

    // attention
    attn_f16_kernel<<<BATCH * NHEADS * (SEQ / 128), 128, ATTN_SMEM>>>(pq, pk, pv, po);

    // output projection
    GemmArgs op;
    op.A = po;
    op.W[0] = op.W[1] = op.W[2] = pwh + 3 * DMODEL * DMODEL;
    op.bias[0] = op.bias[1] = op.bias[2] = bo;
    op.C[0] = op.C[1] = op.C[2] = out;
    op.pos[0] = op.pos[1] = op.pos[2] = nullptr;
    op.layout_bhnd = 0;
    gemm_mma_kernel<<<dim3(8, 32), 256, GEMM_SMEM>>>(op);
}

// round 13
// speedup vs baseline: 2.6596x; 1.0244x over previous
#include <cuda_runtime.h>
#include <cuda_fp16.h>
#include <math.h>
#include <stdint.h>

#define BATCH   2
#define SEQ     2048
#define DMODEL  1024
#define NHEADS  16
#define HDIM    64
#define M_ROWS  (BATCH*SEQ)
#define ROPE_SCALE 0.006135923151542565f      // 2*pi/1024
#define LOG2_1E4_OVER16 0.830482023721841f    // log2(10000)/16
#define QSCALE 0.1803368801111204f            // 0.125 * log2(e)

// Scratch (device globals: allocation-free)
__device__ __half g_q[BATCH*NHEADS*SEQ*HDIM];   // [B,H,N,D] fp16, *0.125*log2e, roped
__device__ __half g_k[BATCH*NHEADS*SEQ*HDIM];   // [B,H,N,D] fp16, roped
__device__ __half g_v[BATCH*NHEADS*HDIM*SEQ];   // [B,H,D,N] fp16 TRANSPOSED
__device__ __half g_o[BATCH*SEQ*DMODEL];        // [B,N,d] fp16
__device__ __half g_xh[M_ROWS*DMODEL];          // x as fp16
__device__ __half g_wh[4*DMODEL*DMODEL];        // Wq,Wk,Wv,Wo as fp16

// ---------------------------------------------------------------------------
// helpers
// ---------------------------------------------------------------------------
__device__ __forceinline__ float fast_exp2(float x) {
    float y;
    asm("ex2.approx.f32 %0, %1;" : "=f"(y) : "f"(x));
    return y;
}
__device__ __forceinline__ uint32_t smem_u32(const void* p) {
    uint32_t a;
    asm("{ .reg .u64 t; cvta.to.shared.u64 t, %1; cvt.u32.u64 %0, t; }"
        : "=r"(a) : "l"(p));
    return a;
}
__device__ __forceinline__ void cp_async16(uint32_t dst, const void* src) {
    asm volatile("cp.async.cg.shared.global [%0], [%1], 16;" :: "r"(dst), "l"(src));
}
#define CP_COMMIT()  asm volatile("cp.async.commit_group;" ::: "memory")
#define CP_WAIT_1()  asm volatile("cp.async.wait_group 1;" ::: "memory")
#define CP_WAIT_0()  asm volatile("cp.async.wait_group 0;" ::: "memory")

__device__ __forceinline__ uint32_t pack_h2(float a, float b) {
    __half2 h = __floats2half2_rn(a, b);
    return *(uint32_t*)&h;
}
__device__ __forceinline__ uint32_t h2exp2_u32(uint32_t x) {
    uint32_t y;
    asm("ex2.approx.f16x2 %0, %1;" : "=r"(y) : "r"(x));
    return y;
}
__device__ __forceinline__ __half2 u2h2(uint32_t x) { return *(__half2*)&x; }

__device__ __forceinline__ void ldsm_x4(uint32_t* r, uint32_t addr) {
    asm volatile("ldmatrix.sync.aligned.m8n8.x4.shared.b16 {%0,%1,%2,%3}, [%4];"
        : "=r"(r[0]), "=r"(r[1]), "=r"(r[2]), "=r"(r[3]) : "r"(addr));
}

// m16n8k16 fp16 MMA, fp32 accumulate
__device__ __forceinline__ void mma_f16(float c[4], const uint32_t a[4],
                                        uint32_t b0, uint32_t b1)
{
    asm volatile(
        "mma.sync.aligned.m16n8k16.row.col.f32.f16.f16.f32 "
        "{%0,%1,%2,%3}, {%4,%5,%6,%7}, {%8,%9}, {%0,%1,%2,%3};\n"
        : "+f"(c[0]), "+f"(c[1]), "+f"(c[2]), "+f"(c[3])
        : "r"(a[0]), "r"(a[1]), "r"(a[2]), "r"(a[3]), "r"(b0), "r"(b1));
}

// ---------------------------------------------------------------------------
// merged fp16 pre-convert
// ---------------------------------------------------------------------------
struct CvtArgs { const float4* src[5]; };
#define NX4 (M_ROWS*DMODEL/4)
#define NW4 (DMODEL*DMODEL/4)

__global__ void cvt_all_kernel(CvtArgs a, uint2* __restrict__ dstX,
                               uint2* __restrict__ dstW)
{
    int i = blockIdx.x * blockDim.x + threadIdx.x;
    float4 v;
    uint2* d;
    if (i < NX4) {
        v = a.src[0][i];
        d = dstX + i;
    } else {
        int j = i - NX4;
        v = a.src[1 + (j >> 18)][j & (NW4 - 1)];
        d = dstW + j;
    }
    *d = make_uint2(pack_h2(v.x, v.y), pack_h2(v.z, v.w));
}

// ---------------------------------------------------------------------------
// fp16 mma GEMM: cp.async + ldmatrix, 3-stage pipeline.
// ---------------------------------------------------------------------------
struct GemmArgs {
    const __half* A;
    const __half* W[3];
    const float*  bias[3];
    void*         C[3];
    const float*  pos[3];
    int layout_bhnd;
};

#define G_STG 32768
#define GEMM_SMEM (3*G_STG)

__global__ __launch_bounds__(256, 2)
void gemm_mma_kernel(GemmArgs args)
{
    extern __shared__ __align__(128) uint8_t smem[];
    const uint32_t sb = smem_u32(smem);

    const int tid  = threadIdx.x;
    const int warp = tid >> 5;
    const int lane = tid & 31;
    const int wm = (warp & 1) * 64;
    const int wn = (warp >> 1) * 32;
    const int proj = blockIdx.x >> 3;
    const int bn   = (blockIdx.x & 7) * 128;
    const int bm   = blockIdx.y * 128;

    const __half* A    = args.A;
    const __half* W    = args.W[proj];
    const float*  bias = args.bias[proj];
    const float*  pos  = args.pos[proj];

    const int cc = tid & 7;
    const int cr = tid >> 3;
    const __half* gA = A + (size_t)(bm + cr) * DMODEL + cc * 8;
    const __half* gB = W + (size_t)(bn + cr) * DMODEL + cc * 8;
    uint32_t cdst[4];
#pragma unroll
    for (int i = 0; i < 4; i++) {
        int R = cr + 32 * i;
        cdst[i] = R * 128 + ((cc ^ (R & 7)) << 4);
    }

#define GEMM_COPY(tile, stage) do { \
    uint32_t _sA = sb + (stage) * G_STG; \
    uint32_t _sB = _sA + 16384; \
    const __half* _ga = gA + (size_t)(tile) * 64; \
    const __half* _gb = gB + (size_t)(tile) * 64; \
    _Pragma("unroll") \
    for (int i = 0; i < 4; i++) { \
        cp_async16(_sA + cdst[i], _ga + (size_t)i * 32 * DMODEL); \
        cp_async16(_sB + cdst[i], _gb + (size_t)i * 32 * DMODEL); \
    } \
} while (0)

    float acc[4][4][4];
#pragma unroll
    for (int mt = 0; mt < 4; mt++)
#pragma unroll
        for (int nt = 0; nt < 4; nt++)
#pragma unroll
            for (int r = 0; r < 4; r++) acc[mt][nt][r] = 0.f;

    GEMM_COPY(0, 0); CP_COMMIT();
    GEMM_COPY(1, 1); CP_COMMIT();

    const int q = lane & 3;
    const int s = lane >> 2;

    const int rlow = lane & 7;
    const int hbit = (lane >> 3) & 1;
    const int qbit = (lane >> 4) & 1;
    uint32_t aSw[4], bSw[4];
#pragma unroll
    for (int kbi = 0; kbi < 4; kbi++) {
        aSw[kbi] = ((uint32_t)((2 * kbi + qbit) ^ rlow)) << 4;
        bSw[kbi] = ((uint32_t)((2 * kbi + hbit) ^ rlow)) << 4;
    }
    const uint32_t aRb = (uint32_t)(wm + hbit * 8 + rlow) * 128;
    const uint32_t bRb = (uint32_t)(wn + qbit * 8 + rlow) * 128 + 16384;

    int ms = 0, ps = 2;
#pragma unroll 1
    for (int k0 = 0; k0 < 16; k0++) {
        if (k0 < 15) CP_WAIT_1(); else CP_WAIT_0();
        __syncthreads();
        if (k0 + 2 < 16) { GEMM_COPY(k0 + 2, ps); CP_COMMIT(); }

        const uint32_t soff = sb + ms * G_STG;

#pragma unroll
        for (int kbi = 0; kbi < 4; kbi++) {
            uint32_t af[4][4];
#pragma unroll
            for (int mt = 0; mt < 4; mt++)
                ldsm_x4(af[mt], soff + aRb + mt * 2048 + aSw[kbi]);
            uint32_t bf[2][4];
#pragma unroll
            for (int ntp = 0; ntp < 2; ntp++)
                ldsm_x4(bf[ntp], soff + bRb + ntp * 2048 + bSw[kbi]);
#pragma unroll
            for (int nt = 0; nt < 4; nt++) {
                uint32_t b0 = bf[nt >> 1][(nt & 1) * 2];
                uint32_t b1 = bf[nt >> 1][(nt & 1) * 2 + 1];
#pragma unroll
                for (int mt = 0; mt < 4; mt++)
                    mma_f16(acc[mt][nt], af[mt], b0, b1);
            }
        }
        ms = (ms == 2) ? 0 : ms + 1;
        ps = (ps == 2) ? 0 : ps + 1;
    }

    // epilogue
    const float scl = (proj == 0 && args.layout_bhnd) ? QSCALE : 1.0f;
#pragma unroll
    for (int nt = 0; nt < 4; nt++) {
        int cg = bn + wn + nt * 8 + 2 * q;
        float bv0 = bias[cg], bv1 = bias[cg + 1];
        int dd = cg & 63;
        int hh = (cg >> 6) & (NHEADS - 1);
        int ip = (dd & 31) >> 1;
        int plane = (dd >> 5) & 1;
        float invf = fast_exp2(-LOG2_1E4_OVER16 * (float)ip) * ROPE_SCALE;
#pragma unroll
        for (int mt = 0; mt < 4; mt++) {
            int r0 = bm + wm + mt * 16 + s;
#pragma unroll
            for (int rr = 0; rr < 2; rr++) {
                int r = r0 + rr * 8;
                float v0 = acc[mt][nt][rr * 2 + 0] + bv0;
                float v1 = acc[mt][nt][rr * 2 + 1] + bv1;
                if (args.layout_bhnd) {
                    int b = r >> 11, n = r & 2047;
                    if (pos) {
                        float ang = pos[((size_t)(b * SEQ + n)) * 2 + plane] * invf;
                        float sn, cs;
                        __sincosf(ang, &sn, &cs);
                        float y0 = v0 * cs - v1 * sn;
                        float y1 = v0 * sn + v1 * cs;
                        v0 = y0; v1 = y1;
                    }
                    __half* Ch = (__half*)args.C[proj];
                    if (proj == 2) {
                        size_t tb = ((size_t)(b * NHEADS + hh) * HDIM + dd) * SEQ + n;
                        Ch[tb]       = __float2half_rn(v0);
                        Ch[tb + SEQ] = __float2half_rn(v1);
                    } else {
                        size_t base = (((size_t)(b * NHEADS + hh)) * SEQ + n) * HDIM + dd;
                        *(uint32_t*)&Ch[base] = pack_h2(v0 * scl, v1 * scl);
                    }
                } else {
                    float* Cf = (float*)args.C[proj];
                    *(float2*)&Cf[(size_t)r * DMODEL + cg] = make_float2(v0, v1);
                }
            }
        }
    }
}

// ---------------------------------------------------------------------------
// Flash attention, deferred-PV pingpong: GEMM1(t) -> GEMM2(t-1) -> softmax(t).
// 4 smem stages so V(t-1) survives the prefetch of tile t+2.
// 128 q-rows/CTA, 4 warps (32x64). K [key64][dim64], V^T [dim64][key64].
// ---------------------------------------------------------------------------
#define AKV_STG 16384              // K 8KB + V 8KB per stage
#define ATTN_SMEM (4*AKV_STG)

__global__ __launch_bounds__(128)
void attn_f16_kernel(const __half* __restrict__ Q, const __half* __restrict__ Kg,
                     const __half* __restrict__ Vg, __half* __restrict__ O)
{
    extern __shared__ __align__(128) uint8_t smem[];
    const uint32_t sb = smem_u32(smem);

    const int tid  = threadIdx.x;
    const int warp = tid >> 5;
    const int lane = tid & 31;
    const int qb = blockIdx.x & 15;
    const int bh = blockIdx.x >> 4;

    const int q = lane & 3;
    const int s = lane >> 2;

    // Q fragments
    const uint32_t* qw = (const uint32_t*)(Q + ((size_t)bh * SEQ + qb * 128) * HDIM);
    uint32_t qf[2][4][4];
#pragma unroll
    for (int mt = 0; mt < 2; mt++) {
        int r = warp * 32 + mt * 16 + s;
#pragma unroll
        for (int ks = 0; ks < 4; ks++) {
            qf[mt][ks][0] = qw[(size_t)r * 32 + ks * 8 + q];
            qf[mt][ks][1] = qw[(size_t)(r + 8) * 32 + ks * 8 + q];
            qf[mt][ks][2] = qw[(size_t)r * 32 + ks * 8 + q + 4];
            qf[mt][ks][3] = qw[(size_t)(r + 8) * 32 + ks * 8 + q + 4];
        }
    }

    float m[2][2], l[2][2];
    float o[2][8][4];
    uint32_t pf[2][8][2];          // P(t-1) fragments, consumed next iteration
#pragma unroll
    for (int mt = 0; mt < 2; mt++) {
        m[mt][0] = -1e30f; m[mt][1] = -1e30f;
        l[mt][0] = 0.f;    l[mt][1] = 0.f;
#pragma unroll
        for (int nt = 0; nt < 8; nt++)
#pragma unroll
            for (int rr = 0; rr < 4; rr++) o[mt][nt][rr] = 0.f;
    }

    const __half* kbp = Kg + (size_t)bh * SEQ * HDIM;            // [key][dim]
    const __half* vbp = Vg + (size_t)bh * HDIM * SEQ;            // [dim][key]

    const int cc  = tid & 7;
    const int r16 = tid >> 3;

#define ATTN_COPY(kt, stage) do { \
    uint32_t _sK = sb + (stage) * AKV_STG; \
    uint32_t _sV = _sK + 8192; \
    _Pragma("unroll") \
    for (int i = 0; i < 4; i++) { \
        int R = r16 + 16 * i; \
        uint32_t _d = R * 128 + ((cc ^ (R & 7)) << 4); \
        cp_async16(_sK + _d, kbp + (size_t)((kt) + R) * HDIM + cc * 8); \
        cp_async16(_sV + _d, vbp + (size_t)R * SEQ + (kt) + cc * 8); \
    } \
} while (0)

    ATTN_COPY(0, 0);  CP_COMMIT();
    ATTN_COPY(64, 1); CP_COMMIT();

    // ldmatrix B addressing
    const int rlow = lane & 7;
    const int hbit = (lane >> 3) & 1;
    const int qbit = (lane >> 4) & 1;
    uint32_t kSw[4];
#pragma unroll
    for (int ks = 0; ks < 4; ks++)
        kSw[ks] = ((uint32_t)((2 * ks + hbit) ^ rlow)) << 4;
    const uint32_t nRb = (uint32_t)(qbit * 8 + rlow) * 128;

#pragma unroll 1
    for (int t = 0; t < 32; t++) {
        if (t < 31) CP_WAIT_1(); else CP_WAIT_0();
        __syncthreads();
        if (t + 2 < 32) { ATTN_COPY((t + 2) * 64, (t + 2) & 3); CP_COMMIT(); }

        const uint32_t koff = sb + (t & 3) * AKV_STG;

        // GEMM1: S(t) = Q * K(t)^T  (log2-domain logits)
        float sc[2][8][4];
#pragma unroll
        for (int mt = 0; mt < 2; mt++)
#pragma unroll
            for (int nt = 0; nt < 8; nt++)
#pragma unroll
                for (int rr = 0; rr < 4; rr++) sc[mt][nt][rr] = 0.f;

#pragma unroll
        for (int ks = 0; ks < 4; ks++) {
#pragma unroll
            for (int ntp = 0; ntp < 4; ntp++) {
                uint32_t bf[4];
                ldsm_x4(bf, koff + nRb + ntp * 2048 + kSw[ks]);
                mma_f16(sc[0][2 * ntp],     qf[0][ks], bf[0], bf[1]);
                mma_f16(sc[1][2 * ntp],     qf[1][ks], bf[0], bf[1]);
                mma_f16(sc[0][2 * ntp + 1], qf[0][ks], bf[2], bf[3]);
                mma_f16(sc[1][2 * ntp + 1], qf[1][ks], bf[2], bf[3]);
            }
        }

        // deferred GEMM2: O += P(t-1) * V(t-1)^T — overlaps softmax(t)'s latency
        if (t > 0) {
            const uint32_t vprev = sb + ((t - 1) & 3) * AKV_STG + 8192;
#pragma unroll
            for (int kbi = 0; kbi < 4; kbi++) {
                uint32_t a0[4] = { pf[0][2*kbi][0], pf[0][2*kbi][1],
                                   pf[0][2*kbi+1][0], pf[0][2*kbi+1][1] };
                uint32_t a1[4] = { pf[1][2*kbi][0], pf[1][2*kbi][1],
                                   pf[1][2*kbi+1][0], pf[1][2*kbi+1][1] };
#pragma unroll
                for (int ntp = 0; ntp < 4; ntp++) {
                    uint32_t bf[4];
                    ldsm_x4(bf, vprev + nRb + ntp * 2048 + kSw[kbi]);
                    mma_f16(o[0][2 * ntp],     a0, bf[0], bf[1]);
                    mma_f16(o[1][2 * ntp],     a1, bf[0], bf[1]);
                    mma_f16(o[0][2 * ntp + 1], a0, bf[2], bf[3]);
                    mma_f16(o[1][2 * ntp + 1], a1, bf[2], bf[3]);
                }
            }
        }

        // softmax(t): new max, rescale O (post-add, same association), pack P(t)
#pragma unroll
        for (int mt = 0; mt < 2; mt++) {
            float rm0 = -1e30f, rm1 = -1e30f;
#pragma unroll
            for (int nt = 0; nt < 8; nt++) {
                rm0 = fmaxf(rm0, fmaxf(sc[mt][nt][0], sc[mt][nt][1]));
                rm1 = fmaxf(rm1, fmaxf(sc[mt][nt][2], sc[mt][nt][3]));
            }
            rm0 = fmaxf(rm0, __shfl_xor_sync(0xffffffffu, rm0, 1));
            rm0 = fmaxf(rm0, __shfl_xor_sync(0xffffffffu, rm0, 2));
            rm1 = fmaxf(rm1, __shfl_xor_sync(0xffffffffu, rm1, 1));
            rm1 = fmaxf(rm1, __shfl_xor_sync(0xffffffffu, rm1, 2));

            float mn0 = fmaxf(m[mt][0], rm0), mn1 = fmaxf(m[mt][1], rm1);
            float cr0 = fast_exp2(m[mt][0] - mn0), cr1 = fast_exp2(m[mt][1] - mn1);
            m[mt][0] = mn0; m[mt][1] = mn1;

#pragma unroll
            for (int nt = 0; nt < 8; nt++) {
                pf[mt][nt][0] = h2exp2_u32(pack_h2(sc[mt][nt][0] - mn0, sc[mt][nt][1] - mn0));
                pf[mt][nt][1] = h2exp2_u32(pack_h2(sc[mt][nt][2] - mn1, sc[mt][nt][3] - mn1));
            }

            // l sums via HADD2 tree
#pragma unroll
            for (int half = 0; half < 2; half++) {
                __half2 t01 = __hadd2(u2h2(pf[mt][0][half]), u2h2(pf[mt][1][half]));
                __half2 t23 = __hadd2(u2h2(pf[mt][2][half]), u2h2(pf[mt][3][half]));
                __half2 t45 = __hadd2(u2h2(pf[mt][4][half]), u2h2(pf[mt][5][half]));
                __half2 t67 = __hadd2(u2h2(pf[mt][6][half]), u2h2(pf[mt][7][half]));
                __half2 tt = __hadd2(__hadd2(t01, t23), __hadd2(t45, t67));
                float2 f = __half22float2(tt);
                float sum = f.x + f.y;
                sum += __shfl_xor_sync(0xffffffffu, sum, 1);
                sum += __shfl_xor_sync(0xffffffffu, sum, 2);
                float cr = half ? cr1 : cr0;
                l[mt][half] = l[mt][half] * cr + sum;
            }

            // rescale O to new max (skip exact-noop)
            if (!__all_sync(0xffffffffu, (cr0 == 1.f) && (cr1 == 1.f))) {
#pragma unroll
                for (int nt = 0; nt < 8; nt++) {
                    o[mt][nt][0] *= cr0; o[mt][nt][1] *= cr0;
                    o[mt][nt][2] *= cr1; o[mt][nt][3] *= cr1;
                }
            }
        }
    }

    // final deferred GEMM2: O += P(31) * V(31)^T (stage 31&3 = 3, still valid)
    {
        const uint32_t vlast = sb + 3 * AKV_STG + 8192;
#pragma unroll
        for (int kbi = 0; kbi < 4; kbi++) {
            uint32_t a0[4] = { pf[0][2*kbi][0], pf[0][2*kbi][1],
                               pf[0][2*kbi+1][0], pf[0][2*kbi+1][1] };
            uint32_t a1[4] = { pf[1][2*kbi][0], pf[1][2*kbi][1],
                               pf[1][2*kbi+1][0], pf[1][2*kbi+1][1] };
#pragma unroll
            for (int ntp = 0; ntp < 4; ntp++) {
                uint32_t bf[4];
                ldsm_x4(bf, vlast + nRb + ntp * 2048 + kSw[kbi]);
                mma_f16(o[0][2 * ntp],     a0, bf[0], bf[1]);
                mma_f16(o[1][2 * ntp],     a1, bf[0], bf[1]);
                mma_f16(o[0][2 * ntp + 1], a0, bf[2], bf[3]);
                mma_f16(o[1][2 * ntp + 1], a1, bf[2], bf[3]);
            }
        }
    }

    // finalize -> O half [B,N,DMODEL]
    int b = bh >> 4, h = bh & 15;
#pragma unroll
    for (int mt = 0; mt < 2; mt++) {
        float inv0 = 1.f / l[mt][0], inv1 = 1.f / l[mt][1];
        int n0 = qb * 128 + warp * 32 + mt * 16 + s;
        size_t base0 = ((size_t)(b * SEQ + n0)) * DMODEL + h * HDIM;
        size_t base1 = ((size_t)(b * SEQ + n0 + 8)) * DMODEL + h * HDIM;
#pragma unroll
        for (int nt = 0; nt < 8; nt++) {
            int c0 = nt * 8 + 2 * q;
            *(uint32_t*)&O[base0 + c0] = pack_h2(o[mt][nt][0] * inv0, o[mt][nt][1] * inv0);
            *(uint32_t*)&O[base1 + c0] = pack_h2(o[mt][nt][2] * inv1, o[mt][nt][3] * inv1);
        }
    }
}

// ---------------------------------------------------------------------------
extern "C" void kernel_launch(void* const* d_in, const int* in_sizes, int n_in,
                              void* d_out, int out_size)
{
    const float* x    = (const float*)d_in[0];
    const float* qpos = (const float*)d_in[1];
    const float* kpos = (const float*)d_in[2];
    const float* Wq = (const float*)d_in[3];
    const float* bq = (const float*)d_in[4];
    const float* Wk = (const float*)d_in[5];
    const float* bk = (const float*)d_in[6];
    const float* Wv = (const float*)d_in[7];
    const float* bv = (const float*)d_in[8];
    const float* Wo = (const float*)d_in[9];
    const float* bo = (const float*)d_in[10];
    float* out = (float*)d_out;

    __half *pq, *pk, *pv, *po, *pxh, *pwh;
    cudaGetSymbolAddress((void**)&pq, g_q);
    cudaGetSymbolAddress((void**)&pk, g_k);
    cudaGetSymbolAddress((void**)&pv, g_v);
    cudaGetSymbolAddress((void**)&po, g_o);
    cudaGetSymbolAddress((void**)&pxh, g_xh);
    cudaGetSymbolAddress((void**)&pwh, g_wh);

    cudaFuncSetAttribute(gemm_mma_kernel,
                         cudaFuncAttributeMaxDynamicSharedMemorySize, GEMM_SMEM);
    cudaFuncSetAttribute(attn_f16_kernel,
                         cudaFuncAttributeMaxDynamicSharedMemorySize, ATTN_SMEM);

    // one merged pre-convert launch
    CvtArgs ca;
    ca.src[0] = (const float4*)x;
    ca.src[1] = (const float4*)Wq;
    ca.src[2] = (const float4*)Wk;
    ca.src[3] = (const float4*)Wv;
    ca.src[4] = (const float4*)Wo;
    cvt_all_kernel<<<(NX4 + 4 * NW4) / 256, 256>>>(ca, (uint2*)pxh, (uint2*)pwh);

    // fused QKV projection (+rope; q pre-scaled by 0.125*log2e; V transposed)
    GemmArgs qkv;
    qkv.A = pxh;
    qkv.W[0] = pwh; qkv.W[1] = pwh + DMODEL * DMODEL; qkv.W[2] = pwh + 2 * DMODEL * DMODEL;
    qkv.bias[0] = bq; qkv.bias[1] = bk; qkv.bias[2] = bv;
    qkv.C[0] = pq; qkv.C[1] = pk; qkv.C[2] = pv;
    qkv.pos[0] = qpos; qkv.pos[1] = kpos; qkv.pos[2] = nullptr;
    qkv.layout_bhnd = 1;
    gemm_mma_kernel<<<dim3(24, 32), 256, GEMM_SMEM>>>(qkv);

    // attention
    attn_f16_kernel<<<BATCH * NHEADS * (SEQ / 128), 128, ATTN_SMEM>>>(pq, pk, pv, po);

    // output projection
    GemmArgs op;
    op.A = po;
    op.W[0] = op.W[1] = op.W[2] = pwh + 3 * DMODEL * DMODEL;
    op.bias[0] = op.bias[1] = op.bias[2] = bo;
    op.C[0] = op.C[1] = op.C[2] = out;
    op.pos[0] = op.pos[1] = op.pos[2] = nullptr;
    op.layout_bhnd = 0;
    gemm_mma_kernel<<<dim3(8, 32), 256, GEMM_SMEM>>>(op);
}

// round 14
// speedup vs baseline: 2.7070x; 1.0178x over previous
#include <cuda_runtime.h>
#include <cuda_fp16.h>
#include <math.h>
#include <stdint.h>

#define BATCH   2
#define SEQ     2048
#define DMODEL  1024
#define NHEADS  16
#define HDIM    64
#define M_ROWS  (BATCH*SEQ)
#define ROPE_SCALE 0.006135923151542565f      // 2*pi/1024
#define LOG2_1E4_OVER16 0.830482023721841f    // log2(10000)/16
#define QSCALE 0.1803368801111204f            // 0.125 * log2(e)

// Scratch (device globals: allocation-free)
__device__ __half g_q[BATCH*NHEADS*SEQ*HDIM];   // [B,H,N,D] fp16, *0.125*log2e, roped
__device__ __half g_k[BATCH*NHEADS*SEQ*HDIM];   // [B,H,N,D] fp16, roped
__device__ __half g_v[BATCH*NHEADS*HDIM*SEQ];   // [B,H,D,N] fp16 TRANSPOSED
__device__ __half g_o[BATCH*SEQ*DMODEL];        // [B,N,d] fp16
__device__ __half g_xh[M_ROWS*DMODEL];          // x as fp16
__device__ __half g_wh[4*DMODEL*DMODEL];        // Wq,Wk,Wv,Wo as fp16

// ---------------------------------------------------------------------------
// helpers
// ---------------------------------------------------------------------------
__device__ __forceinline__ float fast_exp2(float x) {
    float y;
    asm("ex2.approx.f32 %0, %1;" : "=f"(y) : "f"(x));
    return y;
}
__device__ __forceinline__ uint32_t smem_u32(const void* p) {
    uint32_t a;
    asm("{ .reg .u64 t; cvta.to.shared.u64 t, %1; cvt.u32.u64 %0, t; }"
        : "=r"(a) : "l"(p));
    return a;
}
__device__ __forceinline__ void cp_async16(uint32_t dst, const void* src) {
    asm volatile("cp.async.cg.shared.global [%0], [%1], 16;" :: "r"(dst), "l"(src));
}
#define CP_COMMIT()  asm volatile("cp.async.commit_group;" ::: "memory")
#define CP_WAIT_1()  asm volatile("cp.async.wait_group 1;" ::: "memory")
#define CP_WAIT_0()  asm volatile("cp.async.wait_group 0;" ::: "memory")

__device__ __forceinline__ uint32_t pack_h2(float a, float b) {
    __half2 h = __floats2half2_rn(a, b);
    return *(uint32_t*)&h;
}
__device__ __forceinline__ uint32_t h2exp2_u32(uint32_t x) {
    uint32_t y;
    asm("ex2.approx.f16x2 %0, %1;" : "=r"(y) : "r"(x));
    return y;
}

__device__ __forceinline__ void ldsm_x4(uint32_t* r, uint32_t addr) {
    asm volatile("ldmatrix.sync.aligned.m8n8.x4.shared.b16 {%0,%1,%2,%3}, [%4];"
        : "=r"(r[0]), "=r"(r[1]), "=r"(r[2]), "=r"(r[3]) : "r"(addr));
}

// m16n8k16 fp16 MMA, fp32 accumulate
__device__ __forceinline__ void mma_f16(float c[4], const uint32_t a[4],
                                        uint32_t b0, uint32_t b1)
{
    asm volatile(
        "mma.sync.aligned.m16n8k16.row.col.f32.f16.f16.f32 "
        "{%0,%1,%2,%3}, {%4,%5,%6,%7}, {%8,%9}, {%0,%1,%2,%3};\n"
        : "+f"(c[0]), "+f"(c[1]), "+f"(c[2]), "+f"(c[3])
        : "r"(a[0]), "r"(a[1]), "r"(a[2]), "r"(a[3]), "r"(b0), "r"(b1));
}

#define ONES_H2 0x3C003C00u   // (1.0h, 1.0h)

// ---------------------------------------------------------------------------
// merged fp16 pre-convert
// ---------------------------------------------------------------------------
struct CvtArgs { const float4* src[5]; };
#define NX4 (M_ROWS*DMODEL/4)
#define NW4 (DMODEL*DMODEL/4)

__global__ void cvt_all_kernel(CvtArgs a, uint2* __restrict__ dstX,
                               uint2* __restrict__ dstW)
{
    int i = blockIdx.x * blockDim.x + threadIdx.x;
    float4 v;
    uint2* d;
    if (i < NX4) {
        v = a.src[0][i];
        d = dstX + i;
    } else {
        int j = i - NX4;
        v = a.src[1 + (j >> 18)][j & (NW4 - 1)];
        d = dstW + j;
    }
    *d = make_uint2(pack_h2(v.x, v.y), pack_h2(v.z, v.w));
}

// ---------------------------------------------------------------------------
// fp16 mma GEMM (unchanged): cp.async + ldmatrix, 3-stage pipeline.
// ---------------------------------------------------------------------------
struct GemmArgs {
    const __half* A;
    const __half* W[3];
    const float*  bias[3];
    void*         C[3];
    const float*  pos[3];
    int layout_bhnd;
};

#define G_STG 32768
#define GEMM_SMEM (3*G_STG)

__global__ __launch_bounds__(256, 2)
void gemm_mma_kernel(GemmArgs args)
{
    extern __shared__ __align__(128) uint8_t smem[];
    const uint32_t sb = smem_u32(smem);

    const int tid  = threadIdx.x;
    const int warp = tid >> 5;
    const int lane = tid & 31;
    const int wm = (warp & 1) * 64;
    const int wn = (warp >> 1) * 32;
    const int proj = blockIdx.x >> 3;
    const int bn   = (blockIdx.x & 7) * 128;
    const int bm   = blockIdx.y * 128;

    const __half* A    = args.A;
    const __half* W    = args.W[proj];
    const float*  bias = args.bias[proj];
    const float*  pos  = args.pos[proj];

    const int cc = tid & 7;
    const int cr = tid >> 3;
    const __half* gA = A + (size_t)(bm + cr) * DMODEL + cc * 8;
    const __half* gB = W + (size_t)(bn + cr) * DMODEL + cc * 8;
    uint32_t cdst[4];
#pragma unroll
    for (int i = 0; i < 4; i++) {
        int R = cr + 32 * i;
        cdst[i] = R * 128 + ((cc ^ (R & 7)) << 4);
    }

#define GEMM_COPY(tile, stage) do { \
    uint32_t _sA = sb + (stage) * G_STG; \
    uint32_t _sB = _sA + 16384; \
    const __half* _ga = gA + (size_t)(tile) * 64; \
    const __half* _gb = gB + (size_t)(tile) * 64; \
    _Pragma("unroll") \
    for (int i = 0; i < 4; i++) { \
        cp_async16(_sA + cdst[i], _ga + (size_t)i * 32 * DMODEL); \
        cp_async16(_sB + cdst[i], _gb + (size_t)i * 32 * DMODEL); \
    } \
} while (0)

    float acc[4][4][4];
#pragma unroll
    for (int mt = 0; mt < 4; mt++)
#pragma unroll
        for (int nt = 0; nt < 4; nt++)
#pragma unroll
            for (int r = 0; r < 4; r++) acc[mt][nt][r] = 0.f;

    GEMM_COPY(0, 0); CP_COMMIT();
    GEMM_COPY(1, 1); CP_COMMIT();

    const int q = lane & 3;
    const int s = lane >> 2;

    const int rlow = lane & 7;
    const int hbit = (lane >> 3) & 1;
    const int qbit = (lane >> 4) & 1;
    uint32_t aSw[4], bSw[4];
#pragma unroll
    for (int kbi = 0; kbi < 4; kbi++) {
        aSw[kbi] = ((uint32_t)((2 * kbi + qbit) ^ rlow)) << 4;
        bSw[kbi] = ((uint32_t)((2 * kbi + hbit) ^ rlow)) << 4;
    }
    const uint32_t aRb = (uint32_t)(wm + hbit * 8 + rlow) * 128;
    const uint32_t bRb = (uint32_t)(wn + qbit * 8 + rlow) * 128 + 16384;

    int ms = 0, ps = 2;
#pragma unroll 1
    for (int k0 = 0; k0 < 16; k0++) {
        if (k0 < 15) CP_WAIT_1(); else CP_WAIT_0();
        __syncthreads();
        if (k0 + 2 < 16) { GEMM_COPY(k0 + 2, ps); CP_COMMIT(); }

        const uint32_t soff = sb + ms * G_STG;

#pragma unroll
        for (int kbi = 0; kbi < 4; kbi++) {
            uint32_t af[4][4];
#pragma unroll
            for (int mt = 0; mt < 4; mt++)
                ldsm_x4(af[mt], soff + aRb + mt * 2048 + aSw[kbi]);
            uint32_t bf[2][4];
#pragma unroll
            for (int ntp = 0; ntp < 2; ntp++)
                ldsm_x4(bf[ntp], soff + bRb + ntp * 2048 + bSw[kbi]);
#pragma unroll
            for (int nt = 0; nt < 4; nt++) {
                uint32_t b0 = bf[nt >> 1][(nt & 1) * 2];
                uint32_t b1 = bf[nt >> 1][(nt & 1) * 2 + 1];
#pragma unroll
                for (int mt = 0; mt < 4; mt++)
                    mma_f16(acc[mt][nt], af[mt], b0, b1);
            }
        }
        ms = (ms == 2) ? 0 : ms + 1;
        ps = (ps == 2) ? 0 : ps + 1;
    }

    // epilogue
    const float scl = (proj == 0 && args.layout_bhnd) ? QSCALE : 1.0f;
#pragma unroll
    for (int nt = 0; nt < 4; nt++) {
        int cg = bn + wn + nt * 8 + 2 * q;
        float bv0 = bias[cg], bv1 = bias[cg + 1];
        int dd = cg & 63;
        int hh = (cg >> 6) & (NHEADS - 1);
        int ip = (dd & 31) >> 1;
        int plane = (dd >> 5) & 1;
        float invf = fast_exp2(-LOG2_1E4_OVER16 * (float)ip) * ROPE_SCALE;
#pragma unroll
        for (int mt = 0; mt < 4; mt++) {
            int r0 = bm + wm + mt * 16 + s;
#pragma unroll
            for (int rr = 0; rr < 2; rr++) {
                int r = r0 + rr * 8;
                float v0 = acc[mt][nt][rr * 2 + 0] + bv0;
                float v1 = acc[mt][nt][rr * 2 + 1] + bv1;
                if (args.layout_bhnd) {
                    int b = r >> 11, n = r & 2047;
                    if (pos) {
                        float ang = pos[((size_t)(b * SEQ + n)) * 2 + plane] * invf;
                        float sn, cs;
                        __sincosf(ang, &sn, &cs);
                        float y0 = v0 * cs - v1 * sn;
                        float y1 = v0 * sn + v1 * cs;
                        v0 = y0; v1 = y1;
                    }
                    __half* Ch = (__half*)args.C[proj];
                    if (proj == 2) {
                        size_t tb = ((size_t)(b * NHEADS + hh) * HDIM + dd) * SEQ + n;
                        Ch[tb]       = __float2half_rn(v0);
                        Ch[tb + SEQ] = __float2half_rn(v1);
                    } else {
                        size_t base = (((size_t)(b * NHEADS + hh)) * SEQ + n) * HDIM + dd;
                        *(uint32_t*)&Ch[base] = pack_h2(v0 * scl, v1 * scl);
                    }
                } else {
                    float* Cf = (float*)args.C[proj];
                    *(float2*)&Cf[(size_t)r * DMODEL + cg] = make_float2(v0, v1);
                }
            }
        }
    }
}

// ---------------------------------------------------------------------------
// Flash attention, deferred-PV pingpong + MMA-based l sums (no sum shuffles).
// GEMM1(t) -> GEMM2(t-1)+lMMA(t-1) -> softmax(t). 4 smem stages.
// 128 q-rows/CTA, 4 warps (32x64). K [key64][dim64], V^T [dim64][key64].
// ---------------------------------------------------------------------------
#define AKV_STG 16384              // K 8KB + V 8KB per stage
#define ATTN_SMEM (4*AKV_STG)

__global__ __launch_bounds__(128)
void attn_f16_kernel(const __half* __restrict__ Q, const __half* __restrict__ Kg,
                     const __half* __restrict__ Vg, __half* __restrict__ O)
{
    extern __shared__ __align__(128) uint8_t smem[];
    const uint32_t sb = smem_u32(smem);

    const int tid  = threadIdx.x;
    const int warp = tid >> 5;
    const int lane = tid & 31;
    const int qb = blockIdx.x & 15;
    const int bh = blockIdx.x >> 4;

    const int q = lane & 3;
    const int s = lane >> 2;

    // Q fragments
    const uint32_t* qw = (const uint32_t*)(Q + ((size_t)bh * SEQ + qb * 128) * HDIM);
    uint32_t qf[2][4][4];
#pragma unroll
    for (int mt = 0; mt < 2; mt++) {
        int r = warp * 32 + mt * 16 + s;
#pragma unroll
        for (int ks = 0; ks < 4; ks++) {
            qf[mt][ks][0] = qw[(size_t)r * 32 + ks * 8 + q];
            qf[mt][ks][1] = qw[(size_t)(r + 8) * 32 + ks * 8 + q];
            qf[mt][ks][2] = qw[(size_t)r * 32 + ks * 8 + q + 4];
            qf[mt][ks][3] = qw[(size_t)(r + 8) * 32 + ks * 8 + q + 4];
        }
    }

    float m[2][2];
    float lacc[2][4];              // MMA l-sum accumulators ([0]=row s, [2]=row s+8)
    float o[2][8][4];
    uint32_t pf[2][8][2];          // P(t-1) fragments, consumed next iteration
#pragma unroll
    for (int mt = 0; mt < 2; mt++) {
        m[mt][0] = -1e30f; m[mt][1] = -1e30f;
#pragma unroll
        for (int rr = 0; rr < 4; rr++) lacc[mt][rr] = 0.f;
#pragma unroll
        for (int nt = 0; nt < 8; nt++)
#pragma unroll
            for (int rr = 0; rr < 4; rr++) o[mt][nt][rr] = 0.f;
    }

    const __half* kbp = Kg + (size_t)bh * SEQ * HDIM;            // [key][dim]
    const __half* vbp = Vg + (size_t)bh * HDIM * SEQ;            // [dim][key]

    const int cc  = tid & 7;
    const int r16 = tid >> 3;

#define ATTN_COPY(kt, stage) do { \
    uint32_t _sK = sb + (stage) * AKV_STG; \
    uint32_t _sV = _sK + 8192; \
    _Pragma("unroll") \
    for (int i = 0; i < 4; i++) { \
        int R = r16 + 16 * i; \
        uint32_t _d = R * 128 + ((cc ^ (R & 7)) << 4); \
        cp_async16(_sK + _d, kbp + (size_t)((kt) + R) * HDIM + cc * 8); \
        cp_async16(_sV + _d, vbp + (size_t)R * SEQ + (kt) + cc * 8); \
    } \
} while (0)

    ATTN_COPY(0, 0);  CP_COMMIT();
    ATTN_COPY(64, 1); CP_COMMIT();

    // ldmatrix B addressing
    const int rlow = lane & 7;
    const int hbit = (lane >> 3) & 1;
    const int qbit = (lane >> 4) & 1;
    uint32_t kSw[4];
#pragma unroll
    for (int ks = 0; ks < 4; ks++)
        kSw[ks] = ((uint32_t)((2 * ks + hbit) ^ rlow)) << 4;
    const uint32_t nRb = (uint32_t)(qbit * 8 + rlow) * 128;

#pragma unroll 1
    for (int t = 0; t < 32; t++) {
        if (t < 31) CP_WAIT_1(); else CP_WAIT_0();
        __syncthreads();
        if (t + 2 < 32) { ATTN_COPY((t + 2) * 64, (t + 2) & 3); CP_COMMIT(); }

        const uint32_t koff = sb + (t & 3) * AKV_STG;

        // GEMM1: S(t) = Q * K(t)^T  (log2-domain logits)
        float sc[2][8][4];
#pragma unroll
        for (int mt = 0; mt < 2; mt++)
#pragma unroll
            for (int nt = 0; nt < 8; nt++)
#pragma unroll
                for (int rr = 0; rr < 4; rr++) sc[mt][nt][rr] = 0.f;

#pragma unroll
        for (int ks = 0; ks < 4; ks++) {
#pragma unroll
            for (int ntp = 0; ntp < 4; ntp++) {
                uint32_t bf[4];
                ldsm_x4(bf, koff + nRb + ntp * 2048 + kSw[ks]);
                mma_f16(sc[0][2 * ntp],     qf[0][ks], bf[0], bf[1]);
                mma_f16(sc[1][2 * ntp],     qf[1][ks], bf[0], bf[1]);
                mma_f16(sc[0][2 * ntp + 1], qf[0][ks], bf[2], bf[3]);
                mma_f16(sc[1][2 * ntp + 1], qf[1][ks], bf[2], bf[3]);
            }
        }

        // deferred GEMM2 + l-MMA: O += P(t-1) V(t-1)^T, lacc += P(t-1)·1
        if (t > 0) {
            const uint32_t vprev = sb + ((t - 1) & 3) * AKV_STG + 8192;
#pragma unroll
            for (int kbi = 0; kbi < 4; kbi++) {
                uint32_t a0[4] = { pf[0][2*kbi][0], pf[0][2*kbi][1],
                                   pf[0][2*kbi+1][0], pf[0][2*kbi+1][1] };
                uint32_t a1[4] = { pf[1][2*kbi][0], pf[1][2*kbi][1],
                                   pf[1][2*kbi+1][0], pf[1][2*kbi+1][1] };
#pragma unroll
                for (int ntp = 0; ntp < 4; ntp++) {
                    uint32_t bf[4];
                    ldsm_x4(bf, vprev + nRb + ntp * 2048 + kSw[kbi]);
                    mma_f16(o[0][2 * ntp],     a0, bf[0], bf[1]);
                    mma_f16(o[1][2 * ntp],     a1, bf[0], bf[1]);
                    mma_f16(o[0][2 * ntp + 1], a0, bf[2], bf[3]);
                    mma_f16(o[1][2 * ntp + 1], a1, bf[2], bf[3]);
                }
                mma_f16(lacc[0], a0, ONES_H2, ONES_H2);
                mma_f16(lacc[1], a1, ONES_H2, ONES_H2);
            }
        }

        // softmax(t): new max, rescale O+lacc, pack P(t). No sum shuffles.
#pragma unroll
        for (int mt = 0; mt < 2; mt++) {
            float rm0 = -1e30f, rm1 = -1e30f;
#pragma unroll
            for (int nt = 0; nt < 8; nt++) {
                rm0 = fmaxf(rm0, fmaxf(sc[mt][nt][0], sc[mt][nt][1]));
                rm1 = fmaxf(rm1, fmaxf(sc[mt][nt][2], sc[mt][nt][3]));
            }
            rm0 = fmaxf(rm0, __shfl_xor_sync(0xffffffffu, rm0, 1));
            rm0 = fmaxf(rm0, __shfl_xor_sync(0xffffffffu, rm0, 2));
            rm1 = fmaxf(rm1, __shfl_xor_sync(0xffffffffu, rm1, 1));
            rm1 = fmaxf(rm1, __shfl_xor_sync(0xffffffffu, rm1, 2));

            float mn0 = fmaxf(m[mt][0], rm0), mn1 = fmaxf(m[mt][1], rm1);
            float cr0 = fast_exp2(m[mt][0] - mn0), cr1 = fast_exp2(m[mt][1] - mn1);
            m[mt][0] = mn0; m[mt][1] = mn1;

#pragma unroll
            for (int nt = 0; nt < 8; nt++) {
                pf[mt][nt][0] = h2exp2_u32(pack_h2(sc[mt][nt][0] - mn0, sc[mt][nt][1] - mn0));
                pf[mt][nt][1] = h2exp2_u32(pack_h2(sc[mt][nt][2] - mn1, sc[mt][nt][3] - mn1));
            }

            // rescale O and lacc to the new max (skip exact-noop)
            if (!__all_sync(0xffffffffu, (cr0 == 1.f) && (cr1 == 1.f))) {
                lacc[mt][0] *= cr0;
                lacc[mt][2] *= cr1;
#pragma unroll
                for (int nt = 0; nt < 8; nt++) {
                    o[mt][nt][0] *= cr0; o[mt][nt][1] *= cr0;
                    o[mt][nt][2] *= cr1; o[mt][nt][3] *= cr1;
                }
            }
        }
    }

    // final deferred GEMM2 + l-MMA for P(31) (stage 3 still valid)
    {
        const uint32_t vlast = sb + 3 * AKV_STG + 8192;
#pragma unroll
        for (int kbi = 0; kbi < 4; kbi++) {
            uint32_t a0[4] = { pf[0][2*kbi][0], pf[0][2*kbi][1],
                               pf[0][2*kbi+1][0], pf[0][2*kbi+1][1] };
            uint32_t a1[4] = { pf[1][2*kbi][0], pf[1][2*kbi][1],
                               pf[1][2*kbi+1][0], pf[1][2*kbi+1][1] };
#pragma unroll
            for (int ntp = 0; ntp < 4; ntp++) {
                uint32_t bf[4];
                ldsm_x4(bf, vlast + nRb + ntp * 2048 + kSw[kbi]);
                mma_f16(o[0][2 * ntp],     a0, bf[0], bf[1]);
                mma_f16(o[1][2 * ntp],     a1, bf[0], bf[1]);
                mma_f16(o[0][2 * ntp + 1], a0, bf[2], bf[3]);
                mma_f16(o[1][2 * ntp + 1], a1, bf[2], bf[3]);
            }
            mma_f16(lacc[0], a0, ONES_H2, ONES_H2);
            mma_f16(lacc[1], a1, ONES_H2, ONES_H2);
        }
    }

    // finalize -> O half [B,N,DMODEL]
    int b = bh >> 4, h = bh & 15;
#pragma unroll
    for (int mt = 0; mt < 2; mt++) {
        float inv0 = 1.f / lacc[mt][0], inv1 = 1.f / lacc[mt][2];
        int n0 = qb * 128 + warp * 32 + mt * 16 + s;
        size_t base0 = ((size_t)(b * SEQ + n0)) * DMODEL + h * HDIM;
        size_t base1 = ((size_t)(b * SEQ + n0 + 8)) * DMODEL + h * HDIM;
#pragma unroll
        for (int nt = 0; nt < 8; nt++) {
            int c0 = nt * 8 + 2 * q;
            *(uint32_t*)&O[base0 + c0] = pack_h2(o[mt][nt][0] * inv0, o[mt][nt][1] * inv0);
            *(uint32_t*)&O[base1 + c0] = pack_h2(o[mt][nt][2] * inv1, o[mt][nt][3] * inv1);
        }
    }
}

// ---------------------------------------------------------------------------
extern "C" void kernel_launch(void* const* d_in, const int* in_sizes, int n_in,
                              void* d_out, int out_size)
{
    const float* x    = (const float*)d_in[0];
    const float* qpos = (const float*)d_in[1];
    const float* kpos = (const float*)d_in[2];
    const float* Wq = (const float*)d_in[3];
    const float* bq = (const float*)d_in[4];
    const float* Wk = (const float*)d_in[5];
    const float* bk = (const float*)d_in[6];
    const float* Wv = (const float*)d_in[7];
    const float* bv = (const float*)d_in[8];
    const float* Wo = (const float*)d_in[9];
    const float* bo = (const float*)d_in[10];
    float* out = (float*)d_out;

    __half *pq, *pk, *pv, *po, *pxh, *pwh;
    cudaGetSymbolAddress((void**)&pq, g_q);
    cudaGetSymbolAddress((void**)&pk, g_k);
    cudaGetSymbolAddress((void**)&pv, g_v);
    cudaGetSymbolAddress((void**)&po, g_o);
    cudaGetSymbolAddress((void**)&pxh, g_xh);
    cudaGetSymbolAddress((void**)&pwh, g_wh);

    cudaFuncSetAttribute(gemm_mma_kernel,
                         cudaFuncAttributeMaxDynamicSharedMemorySize, GEMM_SMEM);
    cudaFuncSetAttribute(attn_f16_kernel,
                         cudaFuncAttributeMaxDynamicSharedMemorySize, ATTN_SMEM);

    // one merged pre-convert launch
    CvtArgs ca;
    ca.src[0] = (const float4*)x;
    ca.src[1] = (const float4*)Wq;
    ca.src[2] = (const float4*)Wk;
    ca.src[3] = (const float4*)Wv;
    ca.src[4] = (const float4*)Wo;
    cvt_all_kernel<<<(NX4 + 4 * NW4) / 256, 256>>>(ca, (uint2*)pxh, (uint2*)pwh);

    // fused QKV projection (+rope; q pre-scaled by 0.125*log2e; V transposed)
    GemmArgs qkv;
    qkv.A = pxh;
    qkv.W[0] = pwh; qkv.W[1] = pwh + DMODEL * DMODEL; qkv.W[2] = pwh + 2 * DMODEL * DMODEL;
    qkv.bias[0] = bq; qkv.bias[1] = bk; qkv.bias[2] = bv;
    qkv.C[0] = pq; qkv.C[1] = pk; qkv.C[2] = pv;
    qkv.pos[0] = qpos; qkv.pos[1] = kpos; qkv.pos[2] = nullptr;
    qkv.layout_bhnd = 1;
    gemm_mma_kernel<<<dim3(24, 32), 256, GEMM_SMEM>>>(qkv);

    // attention
    attn_f16_kernel<<<BATCH * NHEADS * (SEQ / 128), 128, ATTN_SMEM>>>(pq, pk, pv, po);

    // output projection
    GemmArgs op;
    op.A = po;
    op.W[0] = op.W[1] = op.W[2] = pwh + 3 * DMODEL * DMODEL;
    op.bias[0] = op.bias[1] = op.bias[2] = bo;
    op.C[0] = op.C[1] = op.C[2] = out;
    op.pos[0] = op.pos[1] = op.pos[2] = nullptr;
    op.layout_bhnd = 0;
    gemm_mma_kernel<<<dim3(8, 32), 256, GEMM_SMEM>>>(op);
}